// round 3
// baseline (speedup 1.0000x reference)
#include <cuda_runtime.h>
#include <math.h>
#include <float.h>

#define BB   2
#define QN   30
#define WAYS 5
#define SHOTS 5
#define TOPK 5
#define DIMC 64
#define HWC  441
#define HWP  448           // padded HW stride (zeros), 448 = 14*32
#define NSUP (WAYS*SHOTS)  // 25
#define LFE  15
#define SHW  (SHOTS*HWC)   // 2205
#define NTILE 7            // ceil(441/64)

typedef unsigned long long ull;

// ---------------- scratch ----------------
__device__ float g_qn [BB*QN*DIMC*HWP];     // normalized q [n][d][h] (h padded w/ zeros)
__device__ float g_sn [BB*NSUP*DIMC*HWP];   // normalized s [n][d][h]
__device__ float g_qnT[BB*QN*HWC*DIMC];     // transposed   [n][h][d]
__device__ float g_snT[BB*NSUP*HWC*DIMC];
__device__ float g_qpool[BB*QN*DIMC];
__device__ float g_spool[BB*NSUP*DIMC];
__device__ float g_feats[BB*QN*LFE];        // 0..4 cos, 5..9 sim_l (after merge)
__device__ float g_pix[BB*QN*WAYS*NTILE];
__device__ float g_chc[BB*QN*WAYS*4*DIMC*TOPK];  // per-quarter per-d top5

// packed fp32x2 FMA (Blackwell): d = a*b + d elementwise on 2 floats
__device__ __forceinline__ void ffma2(ull &d, ull a, ull b) {
    asm("fma.rn.f32x2 %0, %1, %2, %0;" : "+l"(d) : "l"(a), "l"(b));
}
__device__ __forceinline__ float2 upk(ull v) {
    float2 f; asm("mov.b64 {%0,%1}, %2;" : "=f"(f.x), "=f"(f.y) : "l"(v)); return f;
}

// sorted-descending top-5 insert
__device__ __forceinline__ void ins5(float (&t)[TOPK], float v) {
    if (v > t[TOPK-1]) {
        float x = v;
        #pragma unroll
        for (int i = 0; i < TOPK; i++) {
            float hi = fmaxf(t[i], x);
            x = fminf(t[i], x);
            t[i] = hi;
        }
    }
}

// ---------------- L2-normalize + mean-pool + padded & transposed writes ----------------
template<int IS_S>
__global__ void __launch_bounds__(256) knorm_kernel(const float* __restrict__ x) {
    const int n = blockIdx.x;
    float* __restrict__ xo   = (IS_S ? g_sn  : g_qn)  + (size_t)n * DIMC * HWP;
    float* __restrict__ xT   = (IS_S ? g_snT : g_qnT) + (size_t)n * HWC * DIMC;
    float* __restrict__ pool = (IS_S ? g_spool : g_qpool) + n * DIMC;
    const float* __restrict__ xr = x + (size_t)n * DIMC * HWC;
    __shared__ float inv[DIMC];
    __shared__ float tile[32][65];
    const int t = threadIdx.x, warp = t >> 5, lane = t & 31;

    for (int d = warp; d < DIMC; d += 8) {
        const float* row = xr + d * HWC;
        float ss = 0.f, sm = 0.f;
        for (int h = lane; h < HWC; h += 32) {
            float v = row[h];
            ss = fmaf(v, v, ss);
            sm += v;
        }
        #pragma unroll
        for (int o = 16; o; o >>= 1) {
            ss += __shfl_xor_sync(0xffffffffu, ss, o);
            sm += __shfl_xor_sync(0xffffffffu, sm, o);
        }
        if (lane == 0) {
            inv[d] = 1.0f / sqrtf(ss);
            pool[d] = sm * (1.0f / HWC);
        }
    }
    __syncthreads();

    for (int h0 = 0; h0 < HWP; h0 += 32) {
        #pragma unroll
        for (int p = 0; p < 8; p++) {
            int d = (t >> 5) + p * 8, hh = t & 31, h = h0 + hh;
            float v = (h < HWC) ? xr[d * HWC + h] * inv[d] : 0.f;
            xo[d * HWP + h] = v;
            tile[hh][d] = v;
        }
        __syncthreads();
        if (h0 < HWC) {
            #pragma unroll
            for (int p = 0; p < 8; p++) {          // FIX: was p<4 — only half the tile was transposed
                int d = t & 63, hh = (t >> 6) + p * 4, h = h0 + hh;
                if (h < HWC) xT[(size_t)h * DIMC + d] = tile[hh][d];
            }
        }
        __syncthreads();
    }
}

// ---------------- prototypes + cosine logits ----------------
__global__ void __launch_bounds__(256) kcos_kernel() {
    const int b = blockIdx.x, t = threadIdx.x;
    __shared__ float proto[WAYS * DIMC];
    __shared__ float pin[WAYS], qin[QN];
    for (int i = t; i < WAYS * DIMC; i += 256) {
        int w = i / DIMC, d = i - w * DIMC;
        float s = 0.f;
        #pragma unroll
        for (int k = 0; k < SHOTS; k++)
            s += g_spool[(b*NSUP + w*SHOTS + k)*DIMC + d];
        proto[i] = s * (1.0f / SHOTS);
    }
    __syncthreads();
    for (int i = t; i < WAYS + QN; i += 256) {
        if (i < WAYS) {
            float ss = 0.f;
            for (int d = 0; d < DIMC; d++) { float v = proto[i*DIMC + d]; ss = fmaf(v, v, ss); }
            pin[i] = 1.0f / sqrtf(ss);
        } else {
            int q = i - WAYS;
            float ss = 0.f;
            for (int d = 0; d < DIMC; d++) { float v = g_qpool[(b*QN + q)*DIMC + d]; ss = fmaf(v, v, ss); }
            qin[q] = 1.0f / sqrtf(ss);
        }
    }
    __syncthreads();
    for (int i = t; i < QN * WAYS; i += 256) {
        int q = i / WAYS, w = i - q * WAYS;
        float dot = 0.f;
        for (int d = 0; d < DIMC; d++)
            dot = fmaf(g_qpool[(b*QN + q)*DIMC + d], proto[w*DIMC + d], dot);
        g_feats[(b*QN + q)*LFE + w] = dot * qin[q] * pin[w];
    }
}

// ---------------- channel-level sim: C[64d][80j] per quarter, K=448 (k-packed f32x2) ----------------
__global__ void __launch_bounds__(256, 2) kchan_kernel() {
    const int w = blockIdx.x >> 2, quarter = blockIdx.x & 3;
    const int q = blockIdx.y, b = blockIdx.z;
    __shared__ float smem[5184];                     // As 64x36 + Bs 80x36 == cand 64x81
    float (*As)[36] = (float(*)[36])smem;
    float (*Bs)[36] = (float(*)[36])(smem + 64*36);
    const int t = threadIdx.x, tx = t & 15, ty = t >> 4;
    const float* __restrict__ qbase = g_qn + (size_t)(b*QN + q) * DIMC * HWP;
    const float* __restrict__ sbase = g_sn + (size_t)(b*NSUP + w*SHOTS) * DIMC * HWP;
    const int jbase = quarter * 80;

    ull acc[4][5];
    #pragma unroll
    for (int r = 0; r < 4; r++)
        #pragma unroll
        for (int c = 0; c < 5; c++) acc[r][c] = 0ull;

    for (int h0 = 0; h0 < HWP; h0 += 32) {
        __syncthreads();
        #pragma unroll
        for (int it = 0; it < 2; it++) {
            int idx = t + it * 256; int d = idx >> 3, k4 = idx & 7;
            *(float4*)&As[d][k4*4] = *(const float4*)&qbase[d*HWP + h0 + k4*4];
        }
        for (int idx = t; idx < 640; idx += 256) {
            int jl = idx >> 3, k4 = idx & 7;
            int j = jbase + jl;
            int shot = j >> 6, dd = j & 63;
            *(float4*)&Bs[jl][k4*4] =
                *(const float4*)&sbase[(size_t)(shot*DIMC + dd)*HWP + h0 + k4*4];
        }
        __syncthreads();
        #pragma unroll
        for (int k4 = 0; k4 < 8; k4++) {
            ull a0[4], a1[4];
            #pragma unroll
            for (int r = 0; r < 4; r++) {
                a0[r] = *(const ull*)&As[ty*4 + r][k4*4];
                a1[r] = *(const ull*)&As[ty*4 + r][k4*4 + 2];
            }
            #pragma unroll
            for (int c = 0; c < 5; c++) {
                ull b0 = *(const ull*)&Bs[tx + 16*c][k4*4];
                ull b1 = *(const ull*)&Bs[tx + 16*c][k4*4 + 2];
                #pragma unroll
                for (int r = 0; r < 4; r++) {
                    ffma2(acc[r][c], a0[r], b0);
                    ffma2(acc[r][c], a1[r], b1);
                }
            }
        }
    }
    __syncthreads();
    float (*cand)[81] = (float(*)[81])smem;
    #pragma unroll
    for (int r = 0; r < 4; r++) {
        float t5[TOPK];
        #pragma unroll
        for (int k = 0; k < TOPK; k++) t5[k] = -FLT_MAX;
        #pragma unroll
        for (int c = 0; c < 5; c++) {
            float2 f = upk(acc[r][c]);
            ins5(t5, f.x + f.y);
        }
        #pragma unroll
        for (int k = 0; k < TOPK; k++) cand[ty*4 + r][tx*TOPK + k] = t5[k];
    }
    __syncthreads();
    if (t < DIMC) {
        float t5[TOPK];
        #pragma unroll
        for (int k = 0; k < TOPK; k++) t5[k] = -FLT_MAX;
        #pragma unroll
        for (int i = 0; i < 80; i++) ins5(t5, cand[t][i]);
        float* dst = g_chc + ((size_t)(((b*QN + q)*WAYS + w)*4 + quarter))*DIMC*TOPK + t*TOPK;
        #pragma unroll
        for (int k = 0; k < TOPK; k++) dst[k] = t5[k];
    }
}

// ---------------- merge 4 quarter top-5s per d, sum over d -> sim_l ----------------
__global__ void __launch_bounds__(64) kmerge_kernel() {
    const int bqw = blockIdx.x;          // (b*QN+q)*WAYS + w
    const int d = threadIdx.x;
    const float* base = g_chc + (size_t)bqw * 4 * DIMC * TOPK;
    float t5[TOPK];
    #pragma unroll
    for (int k = 0; k < TOPK; k++) t5[k] = -FLT_MAX;
    #pragma unroll
    for (int qt = 0; qt < 4; qt++)
        #pragma unroll
        for (int k = 0; k < TOPK; k++)
            ins5(t5, base[(qt*DIMC + d)*TOPK + k]);
    float s = t5[0] + t5[1] + t5[2] + t5[3] + t5[4];
    __shared__ float red[2];
    #pragma unroll
    for (int o = 16; o; o >>= 1) s += __shfl_xor_sync(0xffffffffu, s, o);
    if ((d & 31) == 0) red[d >> 5] = s;
    __syncthreads();
    if (d == 0) {
        int bq = bqw / WAYS, w = bqw % WAYS;
        g_feats[bq*LFE + WAYS + w] = red[0] + red[1];
    }
}

// ---------------- pixel-level sim: 64h x 2205j, K=64 (k-packed f32x2, fused top-5) ----------------
__global__ void __launch_bounds__(256, 2) kpix_kernel() {
    const int tile = blockIdx.x;         // 0..6
    const int w = blockIdx.y;
    const int bq = blockIdx.z;           // 0..59
    const int b = bq / QN;
    __shared__ float smem[64*64 + 64*68];    // As[64][64] + Bs[64][68]
    float (*As)[64] = (float(*)[64])smem;
    float (*Bs)[68] = (float(*)[68])(smem + 64*64);
    const int t = threadIdx.x, tx = t & 15, ty = t >> 4;
    const int h0 = tile * 64;
    const float* __restrict__ qT = g_qnT + (size_t)bq * HWC * DIMC;
    const float* __restrict__ sT = g_snT + (size_t)(b*NSUP + w*SHOTS) * HWC * DIMC;

    #pragma unroll
    for (int it = 0; it < 4; it++) {
        int idx = t + it * 256; int m = idx >> 4, d4 = idx & 15;
        int h = h0 + m;
        float4 v = make_float4(0.f, 0.f, 0.f, 0.f);
        if (h < HWC) v = *(const float4*)&qT[(size_t)h*DIMC + d4*4];
        *(float4*)&As[m][d4*4] = v;
    }

    float top[4][TOPK];
    #pragma unroll
    for (int r = 0; r < 4; r++)
        #pragma unroll
        for (int k = 0; k < TOPK; k++) top[r][k] = -FLT_MAX;

    for (int j0 = 0; j0 < 2240; j0 += 64) {
        __syncthreads();
        #pragma unroll
        for (int it = 0; it < 4; it++) {
            int idx = t + it * 256; int jl = idx >> 4, d4 = idx & 15;
            int j = j0 + jl;
            float4 v = make_float4(0.f, 0.f, 0.f, 0.f);
            if (j < SHW) {
                int shot = j / HWC;
                int h2 = j - shot * HWC;
                v = *(const float4*)&sT[(size_t)(shot*HWC + h2)*DIMC + d4*4];
            }
            *(float4*)&Bs[jl][d4*4] = v;
        }
        __syncthreads();
        ull acc[4][4];
        #pragma unroll
        for (int r = 0; r < 4; r++)
            #pragma unroll
            for (int c = 0; c < 4; c++) acc[r][c] = 0ull;
        #pragma unroll 4
        for (int k4 = 0; k4 < 16; k4++) {
            ull a0[4], a1[4];
            #pragma unroll
            for (int r = 0; r < 4; r++) {
                a0[r] = *(const ull*)&As[ty*4 + r][k4*4];
                a1[r] = *(const ull*)&As[ty*4 + r][k4*4 + 2];
            }
            #pragma unroll
            for (int c = 0; c < 4; c++) {
                ull b0 = *(const ull*)&Bs[tx + 16*c][k4*4];
                ull b1 = *(const ull*)&Bs[tx + 16*c][k4*4 + 2];
                #pragma unroll
                for (int r = 0; r < 4; r++) {
                    ffma2(acc[r][c], a0[r], b0);
                    ffma2(acc[r][c], a1[r], b1);
                }
            }
        }
        #pragma unroll
        for (int c = 0; c < 4; c++) {
            bool valid = (j0 + tx + 16*c) < SHW;
            #pragma unroll
            for (int r = 0; r < 4; r++) {
                float2 f = upk(acc[r][c]);
                float v = valid ? (f.x + f.y) : -FLT_MAX;
                ins5(top[r], v);
            }
        }
    }

    __syncthreads();
    float (*cand)[81] = (float(*)[81])smem;
    #pragma unroll
    for (int r = 0; r < 4; r++)
        #pragma unroll
        for (int k = 0; k < TOPK; k++) cand[ty*4 + r][tx*TOPK + k] = top[r][k];
    __syncthreads();

    float rowsum = 0.f;
    if (t < 64) {
        int h = h0 + t;
        if (h < HWC) {
            float t5[TOPK];
            #pragma unroll
            for (int k = 0; k < TOPK; k++) t5[k] = -FLT_MAX;
            #pragma unroll
            for (int i = 0; i < 80; i++) ins5(t5, cand[t][i]);
            rowsum = t5[0] + t5[1] + t5[2] + t5[3] + t5[4];
        }
    }
    __shared__ float red[2];
    if (t < 64) {
        #pragma unroll
        for (int o = 16; o; o >>= 1) rowsum += __shfl_xor_sync(0xffffffffu, rowsum, o);
        if ((t & 31) == 0) red[t >> 5] = rowsum;
    }
    __syncthreads();
    if (t == 0) g_pix[((size_t)bq*WAYS + w)*NTILE + tile] = red[0] + red[1];
}

// ---------------- BN (batch stats) + dilated conv ----------------
__global__ void __launch_bounds__(256) kfin_kernel(const float* __restrict__ gamma,
                                                   const float* __restrict__ beta,
                                                   const float* __restrict__ cw,
                                                   float* __restrict__ out) {
    const int b = blockIdx.x;
    __shared__ float f[QN][LFE];
    __shared__ float mu[LFE], iv[LFE];
    const int t = threadIdx.x;
    for (int i = t; i < QN * WAYS; i += 256) {
        int q = i / WAYS, w = i - q * WAYS;
        const float* fr = &g_feats[(b*QN + q)*LFE];
        f[q][w]     = fr[w];
        f[q][5 + w] = fr[5 + w];
        float s = 0.f;
        #pragma unroll
        for (int j = 0; j < NTILE; j++)
            s += g_pix[((size_t)(b*QN + q)*WAYS + w)*NTILE + j];
        f[q][10 + w] = s;
    }
    __syncthreads();
    if (t < LFE) {
        float m = 0.f;
        for (int q = 0; q < QN; q++) m += f[q][t];
        m *= (1.0f / QN);
        float v = 0.f;
        for (int q = 0; q < QN; q++) { float d = f[q][t] - m; v = fmaf(d, d, v); }
        v *= (1.0f / QN);
        mu[t] = m;
        iv[t] = 1.0f / sqrtf(v + 1e-5f);
    }
    __syncthreads();
    float w0 = cw[0], w1 = cw[1], w2 = cw[2];
    for (int i = t; i < QN * WAYS; i += 256) {
        int q = i / WAYS, c = i - q * WAYS;
        float b0 = (f[q][c]      - mu[c])      * iv[c]      * gamma[c]      + beta[c];
        float b1 = (f[q][c + 5]  - mu[c + 5])  * iv[c + 5]  * gamma[c + 5]  + beta[c + 5];
        float b2 = (f[q][c + 10] - mu[c + 10]) * iv[c + 10] * gamma[c + 10] + beta[c + 10];
        out[(b*QN + q)*WAYS + c] = w0*b0 + w1*b1 + w2*b2;
    }
}

// ---------------- launch ----------------
extern "C" void kernel_launch(void* const* d_in, const int* in_sizes, int n_in,
                              void* d_out, int out_size) {
    const float* q     = (const float*)d_in[0];
    const float* s     = (const float*)d_in[1];
    const float* gamma = (const float*)d_in[2];
    const float* beta  = (const float*)d_in[3];
    const float* cw    = (const float*)d_in[4];
    float* out = (float*)d_out;

    knorm_kernel<0><<<BB*QN, 256>>>(q);
    knorm_kernel<1><<<BB*NSUP, 256>>>(s);
    kcos_kernel<<<BB, 256>>>();
    kchan_kernel<<<dim3(20, QN, BB), 256>>>();
    kpix_kernel<<<dim3(NTILE, WAYS, BB*QN), 256>>>();
    kmerge_kernel<<<BB*QN*WAYS, 64>>>();
    kfin_kernel<<<BB, 256>>>(gamma, beta, cw, out);
}

// round 7
// speedup vs baseline: 2.5397x; 2.5397x over previous
#include <cuda_runtime.h>
#include <math.h>
#include <float.h>
#include <stdint.h>

#define BB   2
#define QN   30
#define WAYS 5
#define SHOTS 5
#define TOPK 5
#define DIMC 64
#define HWC  441
#define HWP  448
#define NSUP (WAYS*SHOTS)
#define LFE  15
#define SHW  (SHOTS*HWC)   // 2205
#define NTILE 7

typedef unsigned long long ull;

// ---------------- scratch ----------------
__device__ float g_qn [BB*QN*DIMC*HWP];     // normalized q [n][d][h], fp32 (for kchan)
__device__ float g_sn [BB*NSUP*DIMC*HWP];
__device__ float g_qnT[BB*QN*HWC*DIMC];     // transposed [n][h][d], tf32-rounded (for kpix mma)
__device__ float g_snT[BB*NSUP*HWC*DIMC];
__device__ float g_qpool[BB*QN*DIMC];
__device__ float g_spool[BB*NSUP*DIMC];
__device__ float g_feats[BB*QN*LFE];
__device__ float g_pix[BB*QN*WAYS*NTILE];
__device__ float g_chc[BB*QN*WAYS*4*DIMC*TOPK];

// tf32 round: PTX requires a .b32 destination register for cvt.rna.tf32.f32
__device__ __forceinline__ float to_tf32(float x) {
    uint32_t u;
    asm("cvt.rna.tf32.f32 %0, %1;" : "=r"(u) : "f"(x));
    return __uint_as_float(u);
}
__device__ __forceinline__ void ffma2(ull &d, ull a, ull b) {
    asm("fma.rn.f32x2 %0, %1, %2, %0;" : "+l"(d) : "l"(a), "l"(b));
}
__device__ __forceinline__ float2 upk(ull v) {
    float2 f; asm("mov.b64 {%0,%1}, %2;" : "=f"(f.x), "=f"(f.y) : "l"(v)); return f;
}
__device__ __forceinline__ void mma_tf32(float &c0, float &c1, float &c2, float &c3,
                                         uint32_t a0, uint32_t a1, uint32_t a2, uint32_t a3,
                                         uint32_t b0, uint32_t b1) {
    asm("mma.sync.aligned.m16n8k8.row.col.f32.tf32.tf32.f32 "
        "{%0,%1,%2,%3}, {%4,%5,%6,%7}, {%8,%9}, {%0,%1,%2,%3};"
        : "+f"(c0), "+f"(c1), "+f"(c2), "+f"(c3)
        : "r"(a0), "r"(a1), "r"(a2), "r"(a3), "r"(b0), "r"(b1));
}

__device__ __forceinline__ void ins5(float (&t)[TOPK], float v) {
    if (v > t[TOPK-1]) {
        float x = v;
        #pragma unroll
        for (int i = 0; i < TOPK; i++) {
            float hi = fmaxf(t[i], x);
            x = fminf(t[i], x);
            t[i] = hi;
        }
    }
}

// ---------------- L2-normalize + mean-pool + padded & transposed(tf32) writes ----------------
template<int IS_S>
__global__ void __launch_bounds__(256) knorm_kernel(const float* __restrict__ x) {
    const int n = blockIdx.x;
    float* __restrict__ xo   = (IS_S ? g_sn  : g_qn)  + (size_t)n * DIMC * HWP;
    float* __restrict__ xT   = (IS_S ? g_snT : g_qnT) + (size_t)n * HWC * DIMC;
    float* __restrict__ pool = (IS_S ? g_spool : g_qpool) + n * DIMC;
    const float* __restrict__ xr = x + (size_t)n * DIMC * HWC;
    __shared__ float inv[DIMC];
    __shared__ float tile[32][65];
    const int t = threadIdx.x, warp = t >> 5, lane = t & 31;

    for (int d = warp; d < DIMC; d += 8) {
        const float* row = xr + d * HWC;
        float ss = 0.f, sm = 0.f;
        for (int h = lane; h < HWC; h += 32) {
            float v = row[h];
            ss = fmaf(v, v, ss);
            sm += v;
        }
        #pragma unroll
        for (int o = 16; o; o >>= 1) {
            ss += __shfl_xor_sync(0xffffffffu, ss, o);
            sm += __shfl_xor_sync(0xffffffffu, sm, o);
        }
        if (lane == 0) {
            inv[d] = 1.0f / sqrtf(ss);
            pool[d] = sm * (1.0f / HWC);
        }
    }
    __syncthreads();

    for (int h0 = 0; h0 < HWP; h0 += 32) {
        #pragma unroll
        for (int p = 0; p < 8; p++) {
            int d = (t >> 5) + p * 8, hh = t & 31, h = h0 + hh;
            float v = (h < HWC) ? xr[d * HWC + h] * inv[d] : 0.f;
            xo[d * HWP + h] = v;
            tile[hh][d] = to_tf32(v);
        }
        __syncthreads();
        if (h0 < HWC) {
            #pragma unroll
            for (int p = 0; p < 8; p++) {
                int d = t & 63, hh = (t >> 6) + p * 4, h = h0 + hh;
                if (h < HWC) xT[(size_t)h * DIMC + d] = tile[hh][d];
            }
        }
        __syncthreads();
    }
}

// ---------------- prototypes + cosine logits ----------------
__global__ void __launch_bounds__(256) kcos_kernel() {
    const int b = blockIdx.x, t = threadIdx.x;
    __shared__ float proto[WAYS * DIMC];
    __shared__ float pin[WAYS], qin[QN];
    for (int i = t; i < WAYS * DIMC; i += 256) {
        int w = i / DIMC, d = i - w * DIMC;
        float s = 0.f;
        #pragma unroll
        for (int k = 0; k < SHOTS; k++)
            s += g_spool[(b*NSUP + w*SHOTS + k)*DIMC + d];
        proto[i] = s * (1.0f / SHOTS);
    }
    __syncthreads();
    for (int i = t; i < WAYS + QN; i += 256) {
        if (i < WAYS) {
            float ss = 0.f;
            for (int d = 0; d < DIMC; d++) { float v = proto[i*DIMC + d]; ss = fmaf(v, v, ss); }
            pin[i] = 1.0f / sqrtf(ss);
        } else {
            int q = i - WAYS;
            float ss = 0.f;
            for (int d = 0; d < DIMC; d++) { float v = g_qpool[(b*QN + q)*DIMC + d]; ss = fmaf(v, v, ss); }
            qin[q] = 1.0f / sqrtf(ss);
        }
    }
    __syncthreads();
    for (int i = t; i < QN * WAYS; i += 256) {
        int q = i / WAYS, w = i - q * WAYS;
        float dot = 0.f;
        for (int d = 0; d < DIMC; d++)
            dot = fmaf(g_qpool[(b*QN + q)*DIMC + d], proto[w*DIMC + d], dot);
        g_feats[(b*QN + q)*LFE + w] = dot * qin[q] * pin[w];
    }
}

// ---------------- channel-level sim (R3 version, 209us) ----------------
__global__ void __launch_bounds__(256, 2) kchan_kernel() {
    const int w = blockIdx.x >> 2, quarter = blockIdx.x & 3;
    const int q = blockIdx.y, b = blockIdx.z;
    __shared__ float smem[5184];
    float (*As)[36] = (float(*)[36])smem;
    float (*Bs)[36] = (float(*)[36])(smem + 64*36);
    const int t = threadIdx.x, tx = t & 15, ty = t >> 4;
    const float* __restrict__ qbase = g_qn + (size_t)(b*QN + q) * DIMC * HWP;
    const float* __restrict__ sbase = g_sn + (size_t)(b*NSUP + w*SHOTS) * DIMC * HWP;
    const int jbase = quarter * 80;

    ull acc[4][5];
    #pragma unroll
    for (int r = 0; r < 4; r++)
        #pragma unroll
        for (int c = 0; c < 5; c++) acc[r][c] = 0ull;

    for (int h0 = 0; h0 < HWP; h0 += 32) {
        __syncthreads();
        #pragma unroll
        for (int it = 0; it < 2; it++) {
            int idx = t + it * 256; int d = idx >> 3, k4 = idx & 7;
            *(float4*)&As[d][k4*4] = *(const float4*)&qbase[d*HWP + h0 + k4*4];
        }
        for (int idx = t; idx < 640; idx += 256) {
            int jl = idx >> 3, k4 = idx & 7;
            int j = jbase + jl;
            int shot = j >> 6, dd = j & 63;
            *(float4*)&Bs[jl][k4*4] =
                *(const float4*)&sbase[(size_t)(shot*DIMC + dd)*HWP + h0 + k4*4];
        }
        __syncthreads();
        #pragma unroll
        for (int k4 = 0; k4 < 8; k4++) {
            ull a0[4], a1[4];
            #pragma unroll
            for (int r = 0; r < 4; r++) {
                a0[r] = *(const ull*)&As[ty*4 + r][k4*4];
                a1[r] = *(const ull*)&As[ty*4 + r][k4*4 + 2];
            }
            #pragma unroll
            for (int c = 0; c < 5; c++) {
                ull b0 = *(const ull*)&Bs[tx + 16*c][k4*4];
                ull b1 = *(const ull*)&Bs[tx + 16*c][k4*4 + 2];
                #pragma unroll
                for (int r = 0; r < 4; r++) {
                    ffma2(acc[r][c], a0[r], b0);
                    ffma2(acc[r][c], a1[r], b1);
                }
            }
        }
    }
    __syncthreads();
    float (*cand)[81] = (float(*)[81])smem;
    #pragma unroll
    for (int r = 0; r < 4; r++) {
        float t5[TOPK];
        #pragma unroll
        for (int k = 0; k < TOPK; k++) t5[k] = -FLT_MAX;
        #pragma unroll
        for (int c = 0; c < 5; c++) {
            float2 f = upk(acc[r][c]);
            ins5(t5, f.x + f.y);
        }
        #pragma unroll
        for (int k = 0; k < TOPK; k++) cand[ty*4 + r][tx*TOPK + k] = t5[k];
    }
    __syncthreads();
    if (t < DIMC) {
        float t5[TOPK];
        #pragma unroll
        for (int k = 0; k < TOPK; k++) t5[k] = -FLT_MAX;
        #pragma unroll
        for (int i = 0; i < 80; i++) ins5(t5, cand[t][i]);
        float* dst = g_chc + ((size_t)(((b*QN + q)*WAYS + w)*4 + quarter))*DIMC*TOPK + t*TOPK;
        #pragma unroll
        for (int k = 0; k < TOPK; k++) dst[k] = t5[k];
    }
}

__global__ void __launch_bounds__(64) kmerge_kernel() {
    const int bqw = blockIdx.x;
    const int d = threadIdx.x;
    const float* base = g_chc + (size_t)bqw * 4 * DIMC * TOPK;
    float t5[TOPK];
    #pragma unroll
    for (int k = 0; k < TOPK; k++) t5[k] = -FLT_MAX;
    #pragma unroll
    for (int qt = 0; qt < 4; qt++)
        #pragma unroll
        for (int k = 0; k < TOPK; k++)
            ins5(t5, base[(qt*DIMC + d)*TOPK + k]);
    float s = t5[0] + t5[1] + t5[2] + t5[3] + t5[4];
    __shared__ float red[2];
    #pragma unroll
    for (int o = 16; o; o >>= 1) s += __shfl_xor_sync(0xffffffffu, s, o);
    if ((d & 31) == 0) red[d >> 5] = s;
    __syncthreads();
    if (d == 0) {
        int bq = bqw / WAYS, w = bqw % WAYS;
        g_feats[bq*LFE + WAYS + w] = red[0] + red[1];
    }
}

// ---------------- pixel-level sim: TF32 mma.sync, fused register top-5 ----------------
// Per block: C[64h x 2240j], K=64. Warps: 2 m-groups(32 rows) x 4 n-groups(16 cols/chunk).
// smem k-interleaved layout: position p=2i holds k=g*8+i, p=2i+1 holds k=g*8+4+i.
__global__ void __launch_bounds__(256) kpix_kernel() {
    const int tile = blockIdx.x;
    const int w = blockIdx.y;
    const int bq = blockIdx.z;
    const int b = bq / QN;
    __shared__ float As [64][72];
    __shared__ float Bs2[64][72];
    __shared__ float red[2];
    const int t = threadIdx.x, lane = t & 31, wid = t >> 5;
    const int wr = wid >> 2, wc = wid & 3;
    const int h0 = tile * 64;
    const int mrow = wr*32 + (lane >> 2);
    const int kcol = 2 * (lane & 3);
    const float* __restrict__ qT = g_qnT + (size_t)bq * HWC * DIMC;
    const float* __restrict__ sT = g_snT + (size_t)(b*NSUP + w*SHOTS) * HWC * DIMC;

    // fill A (once): interleaved k
    for (int idx = t; idx < 512; idx += 256) {
        int m = idx >> 3, g = idx & 7;
        int h = h0 + m;
        float4 f0 = make_float4(0.f,0.f,0.f,0.f), f1 = f0;
        if (h < HWC) {
            const float* src = qT + (size_t)h * DIMC + g*8;
            f0 = *(const float4*)src;
            f1 = *(const float4*)(src + 4);
        }
        float2* dst = (float2*)&As[m][g*8];
        dst[0] = make_float2(f0.x, f1.x);
        dst[1] = make_float2(f0.y, f1.y);
        dst[2] = make_float2(f0.z, f1.z);
        dst[3] = make_float2(f0.w, f1.w);
    }

    float top[4][TOPK];
    #pragma unroll
    for (int r = 0; r < 4; r++)
        #pragma unroll
        for (int k = 0; k < TOPK; k++) top[r][k] = -FLT_MAX;

    float c[4][4];   // [mt*2+nt][c0..c3]
    #pragma unroll
    for (int i = 0; i < 4; i++)
        #pragma unroll
        for (int j = 0; j < 4; j++) c[i][j] = 0.f;

    for (int cb = 0; cb < 2240; cb += 64) {
        __syncthreads();
        // fill B chunk: rows n (=j local), interleaved k
        for (int idx = t; idx < 512; idx += 256) {
            int n = idx >> 3, g = idx & 7;
            int j = cb + n;
            float4 f0 = make_float4(0.f,0.f,0.f,0.f), f1 = f0;
            if (j < SHW) {
                int shot = j / HWC;
                int h2 = j - shot * HWC;
                const float* src = sT + (size_t)(shot*HWC + h2) * DIMC + g*8;
                f0 = *(const float4*)src;
                f1 = *(const float4*)(src + 4);
            }
            float2* dst = (float2*)&Bs2[n][g*8];
            dst[0] = make_float2(f0.x, f1.x);
            dst[1] = make_float2(f0.y, f1.y);
            dst[2] = make_float2(f0.z, f1.z);
            dst[3] = make_float2(f0.w, f1.w);
        }
        __syncthreads();

        #pragma unroll
        for (int ks = 0; ks < 8; ks++) {
            uint2 aA0 = *(const uint2*)&As[mrow     ][ks*8 + kcol];  // (a0,a2) mt0
            uint2 aA1 = *(const uint2*)&As[mrow + 8 ][ks*8 + kcol];  // (a1,a3) mt0
            uint2 aB0 = *(const uint2*)&As[mrow + 16][ks*8 + kcol];  // mt1
            uint2 aB1 = *(const uint2*)&As[mrow + 24][ks*8 + kcol];
            uint2 b0  = *(const uint2*)&Bs2[wc*16     + (lane>>2)][ks*8 + kcol];
            uint2 b1  = *(const uint2*)&Bs2[wc*16 + 8 + (lane>>2)][ks*8 + kcol];
            mma_tf32(c[0][0], c[0][1], c[0][2], c[0][3], aA0.x, aA1.x, aA0.y, aA1.y, b0.x, b0.y);
            mma_tf32(c[1][0], c[1][1], c[1][2], c[1][3], aA0.x, aA1.x, aA0.y, aA1.y, b1.x, b1.y);
            mma_tf32(c[2][0], c[2][1], c[2][2], c[2][3], aB0.x, aB1.x, aB0.y, aB1.y, b0.x, b0.y);
            mma_tf32(c[3][0], c[3][1], c[3][2], c[3][3], aB0.x, aB1.x, aB0.y, aB1.y, b1.x, b1.y);
        }

        // epilogue: fold into running top-5, reset accum
        #pragma unroll
        for (int mt = 0; mt < 2; mt++) {
            #pragma unroll
            for (int nt = 0; nt < 2; nt++) {
                int col0 = cb + wc*16 + nt*8 + kcol;
                float* cc = c[mt*2 + nt];
                if (col0 < SHW)     ins5(top[mt*2+0], cc[0]);
                if (col0 + 1 < SHW) ins5(top[mt*2+0], cc[1]);
                if (col0 < SHW)     ins5(top[mt*2+1], cc[2]);
                if (col0 + 1 < SHW) ins5(top[mt*2+1], cc[3]);
                cc[0] = cc[1] = cc[2] = cc[3] = 0.f;
            }
        }
    }

    // merge across the 4 lanes sharing each row (lane%4 quad)
    #pragma unroll
    for (int off = 1; off <= 2; off <<= 1) {
        #pragma unroll
        for (int r = 0; r < 4; r++) {
            float other[TOPK];
            #pragma unroll
            for (int k = 0; k < TOPK; k++)
                other[k] = __shfl_xor_sync(0xffffffffu, top[r][k], off);
            #pragma unroll
            for (int k = 0; k < TOPK; k++) ins5(top[r], other[k]);
        }
    }

    __syncthreads();                 // all warps done reading As/Bs2
    float* candbase = &As[0][0];     // reuse As storage: cand[row][21]
    if ((lane & 3) == 0) {
        #pragma unroll
        for (int r = 0; r < 4; r++) {
            int row = mrow + r * 8;
            #pragma unroll
            for (int k = 0; k < TOPK; k++)
                candbase[row * 21 + wc*TOPK + k] = top[r][k];
        }
    }
    __syncthreads();

    float rowsum = 0.f;
    if (t < 64) {
        if (h0 + t < HWC) {
            float t5[TOPK];
            #pragma unroll
            for (int k = 0; k < TOPK; k++) t5[k] = -FLT_MAX;
            #pragma unroll
            for (int i = 0; i < 20; i++) ins5(t5, candbase[t * 21 + i]);
            rowsum = t5[0] + t5[1] + t5[2] + t5[3] + t5[4];
        }
        #pragma unroll
        for (int o = 16; o; o >>= 1) rowsum += __shfl_xor_sync(0xffffffffu, rowsum, o);
        if ((t & 31) == 0) red[t >> 5] = rowsum;
    }
    __syncthreads();
    if (t == 0) g_pix[((size_t)bq*WAYS + w)*NTILE + tile] = red[0] + red[1];
}

// ---------------- BN (batch stats) + dilated conv ----------------
__global__ void __launch_bounds__(256) kfin_kernel(const float* __restrict__ gamma,
                                                   const float* __restrict__ beta,
                                                   const float* __restrict__ cw,
                                                   float* __restrict__ out) {
    const int b = blockIdx.x;
    __shared__ float f[QN][LFE];
    __shared__ float mu[LFE], iv[LFE];
    const int t = threadIdx.x;
    for (int i = t; i < QN * WAYS; i += 256) {
        int q = i / WAYS, w = i - q * WAYS;
        const float* fr = &g_feats[(b*QN + q)*LFE];
        f[q][w]     = fr[w];
        f[q][5 + w] = fr[5 + w];
        float s = 0.f;
        #pragma unroll
        for (int j = 0; j < NTILE; j++)
            s += g_pix[((size_t)(b*QN + q)*WAYS + w)*NTILE + j];
        f[q][10 + w] = s;
    }
    __syncthreads();
    if (t < LFE) {
        float m = 0.f;
        for (int q = 0; q < QN; q++) m += f[q][t];
        m *= (1.0f / QN);
        float v = 0.f;
        for (int q = 0; q < QN; q++) { float d = f[q][t] - m; v = fmaf(d, d, v); }
        v *= (1.0f / QN);
        mu[t] = m;
        iv[t] = 1.0f / sqrtf(v + 1e-5f);
    }
    __syncthreads();
    float w0 = cw[0], w1 = cw[1], w2 = cw[2];
    for (int i = t; i < QN * WAYS; i += 256) {
        int q = i / WAYS, c = i - q * WAYS;
        float b0 = (f[q][c]      - mu[c])      * iv[c]      * gamma[c]      + beta[c];
        float b1 = (f[q][c + 5]  - mu[c + 5])  * iv[c + 5]  * gamma[c + 5]  + beta[c + 5];
        float b2 = (f[q][c + 10] - mu[c + 10]) * iv[c + 10] * gamma[c + 10] + beta[c + 10];
        out[(b*QN + q)*WAYS + c] = w0*b0 + w1*b1 + w2*b2;
    }
}

// ---------------- launch ----------------
extern "C" void kernel_launch(void* const* d_in, const int* in_sizes, int n_in,
                              void* d_out, int out_size) {
    const float* q     = (const float*)d_in[0];
    const float* s     = (const float*)d_in[1];
    const float* gamma = (const float*)d_in[2];
    const float* beta  = (const float*)d_in[3];
    const float* cw    = (const float*)d_in[4];
    float* out = (float*)d_out;

    knorm_kernel<0><<<BB*QN, 256>>>(q);
    knorm_kernel<1><<<BB*NSUP, 256>>>(s);
    kcos_kernel<<<BB, 256>>>();
    kchan_kernel<<<dim3(20, QN, BB), 256>>>();
    kpix_kernel<<<dim3(NTILE, WAYS, BB*QN), 256>>>();
    kmerge_kernel<<<BB*QN*WAYS, 64>>>();
    kfin_kernel<<<BB, 256>>>(gamma, beta, cw, out);
}

// round 10
// speedup vs baseline: 2.9686x; 1.1689x over previous
#include <cuda_runtime.h>
#include <math.h>
#include <float.h>
#include <stdint.h>

#define BB   2
#define QN   30
#define WAYS 5
#define SHOTS 5
#define TOPK 5
#define DIMC 64
#define HWC  441
#define HWP  448
#define NSUP (WAYS*SHOTS)
#define LFE  15
#define SHW  (SHOTS*HWC)   // 2205
#define NTILE 7

// ---------------- scratch ----------------
__device__ float g_qn [BB*QN*DIMC*HWP];     // normalized q [n][d][h], tf32-rounded, h zero-padded
__device__ float g_sn [BB*NSUP*DIMC*HWP];
__device__ float g_qnT[BB*QN*HWC*DIMC];     // transposed [n][h][d], tf32-rounded (for kpix mma)
__device__ float g_snT[BB*NSUP*HWC*DIMC];
__device__ float g_qpool[BB*QN*DIMC];
__device__ float g_spool[BB*NSUP*DIMC];
__device__ float g_feats[BB*QN*LFE];
__device__ float g_pix[BB*QN*WAYS*NTILE];
__device__ float g_chc[BB*QN*WAYS*4*DIMC*TOPK];

// tf32 round: PTX requires a .b32 destination register
__device__ __forceinline__ float to_tf32(float x) {
    uint32_t u;
    asm("cvt.rna.tf32.f32 %0, %1;" : "=r"(u) : "f"(x));
    return __uint_as_float(u);
}
__device__ __forceinline__ void mma_tf32(float &c0, float &c1, float &c2, float &c3,
                                         uint32_t a0, uint32_t a1, uint32_t a2, uint32_t a3,
                                         uint32_t b0, uint32_t b1) {
    asm("mma.sync.aligned.m16n8k8.row.col.f32.tf32.tf32.f32 "
        "{%0,%1,%2,%3}, {%4,%5,%6,%7}, {%8,%9}, {%0,%1,%2,%3};"
        : "+f"(c0), "+f"(c1), "+f"(c2), "+f"(c3)
        : "r"(a0), "r"(a1), "r"(a2), "r"(a3), "r"(b0), "r"(b1));
}

__device__ __forceinline__ void ins5(float (&t)[TOPK], float v) {
    if (v > t[TOPK-1]) {
        float x = v;
        #pragma unroll
        for (int i = 0; i < TOPK; i++) {
            float hi = fmaxf(t[i], x);
            x = fminf(t[i], x);
            t[i] = hi;
        }
    }
}

// ---------------- L2-normalize + mean-pool + padded(tf32) & transposed(tf32) writes ----------------
template<int IS_S>
__global__ void __launch_bounds__(256) knorm_kernel(const float* __restrict__ x) {
    const int n = blockIdx.x;
    float* __restrict__ xo   = (IS_S ? g_sn  : g_qn)  + (size_t)n * DIMC * HWP;
    float* __restrict__ xT   = (IS_S ? g_snT : g_qnT) + (size_t)n * HWC * DIMC;
    float* __restrict__ pool = (IS_S ? g_spool : g_qpool) + n * DIMC;
    const float* __restrict__ xr = x + (size_t)n * DIMC * HWC;
    __shared__ float inv[DIMC];
    __shared__ float tile[32][65];
    const int t = threadIdx.x, warp = t >> 5, lane = t & 31;

    for (int d = warp; d < DIMC; d += 8) {
        const float* row = xr + d * HWC;
        float ss = 0.f, sm = 0.f;
        for (int h = lane; h < HWC; h += 32) {
            float v = row[h];
            ss = fmaf(v, v, ss);
            sm += v;
        }
        #pragma unroll
        for (int o = 16; o; o >>= 1) {
            ss += __shfl_xor_sync(0xffffffffu, ss, o);
            sm += __shfl_xor_sync(0xffffffffu, sm, o);
        }
        if (lane == 0) {
            inv[d] = 1.0f / sqrtf(ss);
            pool[d] = sm * (1.0f / HWC);
        }
    }
    __syncthreads();

    for (int h0 = 0; h0 < HWP; h0 += 32) {
        #pragma unroll
        for (int p = 0; p < 8; p++) {
            int d = (t >> 5) + p * 8, hh = t & 31, h = h0 + hh;
            float v = (h < HWC) ? to_tf32(xr[d * HWC + h] * inv[d]) : 0.f;
            xo[d * HWP + h] = v;
            tile[hh][d] = v;
        }
        __syncthreads();
        if (h0 < HWC) {
            #pragma unroll
            for (int p = 0; p < 8; p++) {
                int d = t & 63, hh = (t >> 6) + p * 4, h = h0 + hh;
                if (h < HWC) xT[(size_t)h * DIMC + d] = tile[hh][d];
            }
        }
        __syncthreads();
    }
}

// ---------------- prototypes + cosine logits ----------------
__global__ void __launch_bounds__(256) kcos_kernel() {
    const int b = blockIdx.x, t = threadIdx.x;
    __shared__ float proto[WAYS * DIMC];
    __shared__ float pin[WAYS], qin[QN];
    for (int i = t; i < WAYS * DIMC; i += 256) {
        int w = i / DIMC, d = i - w * DIMC;
        float s = 0.f;
        #pragma unroll
        for (int k = 0; k < SHOTS; k++)
            s += g_spool[(b*NSUP + w*SHOTS + k)*DIMC + d];
        proto[i] = s * (1.0f / SHOTS);
    }
    __syncthreads();
    for (int i = t; i < WAYS + QN; i += 256) {
        if (i < WAYS) {
            float ss = 0.f;
            for (int d = 0; d < DIMC; d++) { float v = proto[i*DIMC + d]; ss = fmaf(v, v, ss); }
            pin[i] = 1.0f / sqrtf(ss);
        } else {
            int q = i - WAYS;
            float ss = 0.f;
            for (int d = 0; d < DIMC; d++) { float v = g_qpool[(b*QN + q)*DIMC + d]; ss = fmaf(v, v, ss); }
            qin[q] = 1.0f / sqrtf(ss);
        }
    }
    __syncthreads();
    for (int i = t; i < QN * WAYS; i += 256) {
        int q = i / WAYS, w = i - q * WAYS;
        float dot = 0.f;
        for (int d = 0; d < DIMC; d++)
            dot = fmaf(g_qpool[(b*QN + q)*DIMC + d], proto[w*DIMC + d], dot);
        g_feats[(b*QN + q)*LFE + w] = dot * qin[q] * pin[w];
    }
}

// ---------------- channel-level sim: TF32 mma, C[64d x 80j] per quarter, K=448 ----------------
// Warps: 4 m-groups x 2 n-groups. smem k-interleaved like kpix: p=2i <- k=g*8+i, p=2i+1 <- k=g*8+4+i.
__global__ void __launch_bounds__(256) kchan_kernel() {
    const int w = blockIdx.x >> 2, quarter = blockIdx.x & 3;
    const int q = blockIdx.y, b = blockIdx.z;
    __shared__ float As[64][72];
    __shared__ float Bs[80][72];
    const int t = threadIdx.x, lane = t & 31, wid = t >> 5;
    const int wm = wid >> 1, wn = wid & 1;
    const int mrow = wm * 16 + (lane >> 2);
    const int kcol = 2 * (lane & 3);
    const float* __restrict__ qbase = g_qn + (size_t)(b*QN + q) * DIMC * HWP;
    const float* __restrict__ sbase = g_sn + (size_t)(b*NSUP + w*SHOTS) * DIMC * HWP;
    const int jbase = quarter * 80;

    float c[5][4];
    #pragma unroll
    for (int nt = 0; nt < 5; nt++)
        #pragma unroll
        for (int i = 0; i < 4; i++) c[nt][i] = 0.f;

    for (int chunk = 0; chunk < 7; chunk++) {
        const int h0 = chunk * 64;
        __syncthreads();
        // A: 64 rows (d) x 8 k-groups
        for (int idx = t; idx < 512; idx += 256) {
            int m = idx >> 3, g = idx & 7;
            const float* src = qbase + (size_t)m * HWP + h0 + g * 8;
            float4 f0 = *(const float4*)src;
            float4 f1 = *(const float4*)(src + 4);
            float2* dst = (float2*)&As[m][g*8];
            dst[0] = make_float2(f0.x, f1.x);
            dst[1] = make_float2(f0.y, f1.y);
            dst[2] = make_float2(f0.z, f1.z);
            dst[3] = make_float2(f0.w, f1.w);
        }
        // B: 80 rows (j) x 8 k-groups
        for (int idx = t; idx < 640; idx += 256) {
            int jl = idx >> 3, g = idx & 7;
            int j = jbase + jl;
            int shot = j >> 6, dd = j & 63;
            const float* src = sbase + (size_t)(shot*DIMC + dd) * HWP + h0 + g * 8;
            float4 f0 = *(const float4*)src;
            float4 f1 = *(const float4*)(src + 4);
            float2* dst = (float2*)&Bs[jl][g*8];
            dst[0] = make_float2(f0.x, f1.x);
            dst[1] = make_float2(f0.y, f1.y);
            dst[2] = make_float2(f0.z, f1.z);
            dst[3] = make_float2(f0.w, f1.w);
        }
        __syncthreads();
        #pragma unroll
        for (int ks = 0; ks < 8; ks++) {
            uint2 a0 = *(const uint2*)&As[mrow    ][ks*8 + kcol];
            uint2 a1 = *(const uint2*)&As[mrow + 8][ks*8 + kcol];
            #pragma unroll
            for (int nt = 0; nt < 5; nt++) {
                uint2 bb = *(const uint2*)&Bs[wn*40 + nt*8 + (lane>>2)][ks*8 + kcol];
                mma_tf32(c[nt][0], c[nt][1], c[nt][2], c[nt][3],
                         a0.x, a1.x, a0.y, a1.y, bb.x, bb.y);
            }
        }
    }

    // per-thread top-5 for its two rows (all 320 columns are valid)
    float top[2][TOPK];
    #pragma unroll
    for (int r = 0; r < 2; r++)
        #pragma unroll
        for (int k = 0; k < TOPK; k++) top[r][k] = -FLT_MAX;
    #pragma unroll
    for (int nt = 0; nt < 5; nt++) {
        ins5(top[0], c[nt][0]); ins5(top[0], c[nt][1]);
        ins5(top[1], c[nt][2]); ins5(top[1], c[nt][3]);
    }
    // quad-merge (4 lanes share each row)
    #pragma unroll
    for (int off = 1; off <= 2; off <<= 1) {
        #pragma unroll
        for (int r = 0; r < 2; r++) {
            float other[TOPK];
            #pragma unroll
            for (int k = 0; k < TOPK; k++)
                other[k] = __shfl_xor_sync(0xffffffffu, top[r][k], off);
            #pragma unroll
            for (int k = 0; k < TOPK; k++) ins5(top[r], other[k]);
        }
    }

    __syncthreads();                      // done reading As/Bs
    float (*cand)[10] = (float(*)[10])&As[0][0];   // cand[64][10]
    if ((lane & 3) == 0) {
        #pragma unroll
        for (int r = 0; r < 2; r++) {
            int row = mrow + r * 8;
            #pragma unroll
            for (int k = 0; k < TOPK; k++)
                cand[row][wn*TOPK + k] = top[r][k];
        }
    }
    __syncthreads();
    if (t < DIMC) {
        float t5[TOPK];
        #pragma unroll
        for (int k = 0; k < TOPK; k++) t5[k] = -FLT_MAX;
        #pragma unroll
        for (int i = 0; i < 10; i++) ins5(t5, cand[t][i]);
        float* dst = g_chc + ((size_t)(((b*QN + q)*WAYS + w)*4 + quarter))*DIMC*TOPK + t*TOPK;
        #pragma unroll
        for (int k = 0; k < TOPK; k++) dst[k] = t5[k];
    }
}

// ---------------- merge 4 quarter top-5s per d, sum over d -> sim_l ----------------
__global__ void __launch_bounds__(64) kmerge_kernel() {
    const int bqw = blockIdx.x;
    const int d = threadIdx.x;
    const float* base = g_chc + (size_t)bqw * 4 * DIMC * TOPK;
    float t5[TOPK];
    #pragma unroll
    for (int k = 0; k < TOPK; k++) t5[k] = -FLT_MAX;
    #pragma unroll
    for (int qt = 0; qt < 4; qt++)
        #pragma unroll
        for (int k = 0; k < TOPK; k++)
            ins5(t5, base[(qt*DIMC + d)*TOPK + k]);
    float s = t5[0] + t5[1] + t5[2] + t5[3] + t5[4];
    __shared__ float red[2];
    #pragma unroll
    for (int o = 16; o; o >>= 1) s += __shfl_xor_sync(0xffffffffu, s, o);
    if ((d & 31) == 0) red[d >> 5] = s;
    __syncthreads();
    if (d == 0) {
        int bq = bqw / WAYS, w = bqw % WAYS;
        g_feats[bq*LFE + WAYS + w] = red[0] + red[1];
    }
}

// ---------------- pixel-level sim: TF32 mma.sync, fused register top-5 (R7 winner) ----------------
__global__ void __launch_bounds__(256) kpix_kernel() {
    const int tile = blockIdx.x;
    const int w = blockIdx.y;
    const int bq = blockIdx.z;
    const int b = bq / QN;
    __shared__ float As [64][72];
    __shared__ float Bs2[64][72];
    __shared__ float red[2];
    const int t = threadIdx.x, lane = t & 31, wid = t >> 5;
    const int wr = wid >> 2, wc = wid & 3;
    const int h0 = tile * 64;
    const int mrow = wr*32 + (lane >> 2);
    const int kcol = 2 * (lane & 3);
    const float* __restrict__ qT = g_qnT + (size_t)bq * HWC * DIMC;
    const float* __restrict__ sT = g_snT + (size_t)(b*NSUP + w*SHOTS) * HWC * DIMC;

    for (int idx = t; idx < 512; idx += 256) {
        int m = idx >> 3, g = idx & 7;
        int h = h0 + m;
        float4 f0 = make_float4(0.f,0.f,0.f,0.f), f1 = f0;
        if (h < HWC) {
            const float* src = qT + (size_t)h * DIMC + g*8;
            f0 = *(const float4*)src;
            f1 = *(const float4*)(src + 4);
        }
        float2* dst = (float2*)&As[m][g*8];
        dst[0] = make_float2(f0.x, f1.x);
        dst[1] = make_float2(f0.y, f1.y);
        dst[2] = make_float2(f0.z, f1.z);
        dst[3] = make_float2(f0.w, f1.w);
    }

    float top[4][TOPK];
    #pragma unroll
    for (int r = 0; r < 4; r++)
        #pragma unroll
        for (int k = 0; k < TOPK; k++) top[r][k] = -FLT_MAX;

    float c[4][4];
    #pragma unroll
    for (int i = 0; i < 4; i++)
        #pragma unroll
        for (int j = 0; j < 4; j++) c[i][j] = 0.f;

    for (int cb = 0; cb < 2240; cb += 64) {
        __syncthreads();
        for (int idx = t; idx < 512; idx += 256) {
            int n = idx >> 3, g = idx & 7;
            int j = cb + n;
            float4 f0 = make_float4(0.f,0.f,0.f,0.f), f1 = f0;
            if (j < SHW) {
                int shot = j / HWC;
                int h2 = j - shot * HWC;
                const float* src = sT + (size_t)(shot*HWC + h2) * DIMC + g*8;
                f0 = *(const float4*)src;
                f1 = *(const float4*)(src + 4);
            }
            float2* dst = (float2*)&Bs2[n][g*8];
            dst[0] = make_float2(f0.x, f1.x);
            dst[1] = make_float2(f0.y, f1.y);
            dst[2] = make_float2(f0.z, f1.z);
            dst[3] = make_float2(f0.w, f1.w);
        }
        __syncthreads();

        #pragma unroll
        for (int ks = 0; ks < 8; ks++) {
            uint2 aA0 = *(const uint2*)&As[mrow     ][ks*8 + kcol];
            uint2 aA1 = *(const uint2*)&As[mrow + 8 ][ks*8 + kcol];
            uint2 aB0 = *(const uint2*)&As[mrow + 16][ks*8 + kcol];
            uint2 aB1 = *(const uint2*)&As[mrow + 24][ks*8 + kcol];
            uint2 b0  = *(const uint2*)&Bs2[wc*16     + (lane>>2)][ks*8 + kcol];
            uint2 b1  = *(const uint2*)&Bs2[wc*16 + 8 + (lane>>2)][ks*8 + kcol];
            mma_tf32(c[0][0], c[0][1], c[0][2], c[0][3], aA0.x, aA1.x, aA0.y, aA1.y, b0.x, b0.y);
            mma_tf32(c[1][0], c[1][1], c[1][2], c[1][3], aA0.x, aA1.x, aA0.y, aA1.y, b1.x, b1.y);
            mma_tf32(c[2][0], c[2][1], c[2][2], c[2][3], aB0.x, aB1.x, aB0.y, aB1.y, b0.x, b0.y);
            mma_tf32(c[3][0], c[3][1], c[3][2], c[3][3], aB0.x, aB1.x, aB0.y, aB1.y, b1.x, b1.y);
        }

        #pragma unroll
        for (int mt = 0; mt < 2; mt++) {
            #pragma unroll
            for (int nt = 0; nt < 2; nt++) {
                int col0 = cb + wc*16 + nt*8 + kcol;
                float* cc = c[mt*2 + nt];
                if (col0 < SHW)     ins5(top[mt*2+0], cc[0]);
                if (col0 + 1 < SHW) ins5(top[mt*2+0], cc[1]);
                if (col0 < SHW)     ins5(top[mt*2+1], cc[2]);
                if (col0 + 1 < SHW) ins5(top[mt*2+1], cc[3]);
                cc[0] = cc[1] = cc[2] = cc[3] = 0.f;
            }
        }
    }

    #pragma unroll
    for (int off = 1; off <= 2; off <<= 1) {
        #pragma unroll
        for (int r = 0; r < 4; r++) {
            float other[TOPK];
            #pragma unroll
            for (int k = 0; k < TOPK; k++)
                other[k] = __shfl_xor_sync(0xffffffffu, top[r][k], off);
            #pragma unroll
            for (int k = 0; k < TOPK; k++) ins5(top[r], other[k]);
        }
    }

    __syncthreads();
    float* candbase = &As[0][0];
    if ((lane & 3) == 0) {
        #pragma unroll
        for (int r = 0; r < 4; r++) {
            int row = mrow + r * 8;
            #pragma unroll
            for (int k = 0; k < TOPK; k++)
                candbase[row * 21 + wc*TOPK + k] = top[r][k];
        }
    }
    __syncthreads();

    float rowsum = 0.f;
    if (t < 64) {
        if (h0 + t < HWC) {
            float t5[TOPK];
            #pragma unroll
            for (int k = 0; k < TOPK; k++) t5[k] = -FLT_MAX;
            #pragma unroll
            for (int i = 0; i < 20; i++) ins5(t5, candbase[t * 21 + i]);
            rowsum = t5[0] + t5[1] + t5[2] + t5[3] + t5[4];
        }
        #pragma unroll
        for (int o = 16; o; o >>= 1) rowsum += __shfl_xor_sync(0xffffffffu, rowsum, o);
        if ((t & 31) == 0) red[t >> 5] = rowsum;
    }
    __syncthreads();
    if (t == 0) g_pix[((size_t)bq*WAYS + w)*NTILE + tile] = red[0] + red[1];
}

// ---------------- BN (batch stats) + dilated conv ----------------
__global__ void __launch_bounds__(256) kfin_kernel(const float* __restrict__ gamma,
                                                   const float* __restrict__ beta,
                                                   const float* __restrict__ cw,
                                                   float* __restrict__ out) {
    const int b = blockIdx.x;
    __shared__ float f[QN][LFE];
    __shared__ float mu[LFE], iv[LFE];
    const int t = threadIdx.x;
    for (int i = t; i < QN * WAYS; i += 256) {
        int q = i / WAYS, w = i - q * WAYS;
        const float* fr = &g_feats[(b*QN + q)*LFE];
        f[q][w]     = fr[w];
        f[q][5 + w] = fr[5 + w];
        float s = 0.f;
        #pragma unroll
        for (int j = 0; j < NTILE; j++)
            s += g_pix[((size_t)(b*QN + q)*WAYS + w)*NTILE + j];
        f[q][10 + w] = s;
    }
    __syncthreads();
    if (t < LFE) {
        float m = 0.f;
        for (int q = 0; q < QN; q++) m += f[q][t];
        m *= (1.0f / QN);
        float v = 0.f;
        for (int q = 0; q < QN; q++) { float d = f[q][t] - m; v = fmaf(d, d, v); }
        v *= (1.0f / QN);
        mu[t] = m;
        iv[t] = 1.0f / sqrtf(v + 1e-5f);
    }
    __syncthreads();
    float w0 = cw[0], w1 = cw[1], w2 = cw[2];
    for (int i = t; i < QN * WAYS; i += 256) {
        int q = i / WAYS, c = i - q * WAYS;
        float b0 = (f[q][c]      - mu[c])      * iv[c]      * gamma[c]      + beta[c];
        float b1 = (f[q][c + 5]  - mu[c + 5])  * iv[c + 5]  * gamma[c + 5]  + beta[c + 5];
        float b2 = (f[q][c + 10] - mu[c + 10]) * iv[c + 10] * gamma[c + 10] + beta[c + 10];
        out[(b*QN + q)*WAYS + c] = w0*b0 + w1*b1 + w2*b2;
    }
}

// ---------------- launch ----------------
extern "C" void kernel_launch(void* const* d_in, const int* in_sizes, int n_in,
                              void* d_out, int out_size) {
    const float* q     = (const float*)d_in[0];
    const float* s     = (const float*)d_in[1];
    const float* gamma = (const float*)d_in[2];
    const float* beta  = (const float*)d_in[3];
    const float* cw    = (const float*)d_in[4];
    float* out = (float*)d_out;

    knorm_kernel<0><<<BB*QN, 256>>>(q);
    knorm_kernel<1><<<BB*NSUP, 256>>>(s);
    kcos_kernel<<<BB, 256>>>();
    kchan_kernel<<<dim3(20, QN, BB), 256>>>();
    kpix_kernel<<<dim3(NTILE, WAYS, BB*QN), 256>>>();
    kmerge_kernel<<<BB*QN*WAYS, 64>>>();
    kfin_kernel<<<BB, 256>>>(gamma, beta, cw, out);
}

// round 11
// speedup vs baseline: 3.6832x; 1.2407x over previous
#include <cuda_runtime.h>
#include <math.h>
#include <float.h>
#include <stdint.h>

#define BB   2
#define QN   30
#define WAYS 5
#define SHOTS 5
#define TOPK 5
#define DIMC 64
#define HWC  441
#define HWP  448
#define NSUP (WAYS*SHOTS)
#define LFE  15
#define SHW  (SHOTS*HWC)   // 2205
#define NTILE 7

// ---------------- scratch ----------------
__device__ float g_qn [BB*QN*DIMC*HWP];     // normalized q [n][d][h], tf32-rounded, h zero-padded
__device__ float g_sn [BB*NSUP*DIMC*HWP];
__device__ float g_qnT[BB*QN*HWC*DIMC];     // transposed [n][h][perm(d)], tf32 (kpix mma layout)
__device__ float g_snT[BB*NSUP*HWC*DIMC];
__device__ float g_qpool[BB*QN*DIMC];
__device__ float g_spool[BB*NSUP*DIMC];
__device__ float g_feats[BB*QN*LFE];
__device__ float g_pix[BB*QN*WAYS*NTILE];
__device__ float g_chc[BB*QN*WAYS*4*DIMC*TOPK];

// tf32 round: PTX requires a .b32 destination register
__device__ __forceinline__ float to_tf32(float x) {
    uint32_t u;
    asm("cvt.rna.tf32.f32 %0, %1;" : "=r"(u) : "f"(x));
    return __uint_as_float(u);
}
__device__ __forceinline__ void mma_tf32(float &c0, float &c1, float &c2, float &c3,
                                         uint32_t a0, uint32_t a1, uint32_t a2, uint32_t a3,
                                         uint32_t b0, uint32_t b1) {
    asm("mma.sync.aligned.m16n8k8.row.col.f32.tf32.tf32.f32 "
        "{%0,%1,%2,%3}, {%4,%5,%6,%7}, {%8,%9}, {%0,%1,%2,%3};"
        : "+f"(c0), "+f"(c1), "+f"(c2), "+f"(c3)
        : "r"(a0), "r"(a1), "r"(a2), "r"(a3), "r"(b0), "r"(b1));
}
__device__ __forceinline__ void cp_async16(uint32_t dst, const void* src) {
    asm volatile("cp.async.cg.shared.global [%0], [%1], 16;" :: "r"(dst), "l"(src));
}
__device__ __forceinline__ void cp_commit() {
    asm volatile("cp.async.commit_group;");
}

__device__ __forceinline__ void ins5(float (&t)[TOPK], float v) {
    if (v > t[TOPK-1]) {
        float x = v;
        #pragma unroll
        for (int i = 0; i < TOPK; i++) {
            float hi = fmaxf(t[i], x);
            x = fminf(t[i], x);
            t[i] = hi;
        }
    }
}

// ---------------- L2-normalize + mean-pool + padded(tf32) & perm-transposed(tf32) ----------------
template<int IS_S>
__global__ void __launch_bounds__(256) knorm_kernel(const float* __restrict__ x) {
    const int n = blockIdx.x;
    float* __restrict__ xo   = (IS_S ? g_sn  : g_qn)  + (size_t)n * DIMC * HWP;
    float* __restrict__ xT   = (IS_S ? g_snT : g_qnT) + (size_t)n * HWC * DIMC;
    float* __restrict__ pool = (IS_S ? g_spool : g_qpool) + n * DIMC;
    const float* __restrict__ xr = x + (size_t)n * DIMC * HWC;
    __shared__ float inv[DIMC];
    __shared__ float tile[32][65];
    const int t = threadIdx.x, warp = t >> 5, lane = t & 31;

    for (int d = warp; d < DIMC; d += 8) {
        const float* row = xr + d * HWC;
        float ss = 0.f, sm = 0.f;
        for (int h = lane; h < HWC; h += 32) {
            float v = row[h];
            ss = fmaf(v, v, ss);
            sm += v;
        }
        #pragma unroll
        for (int o = 16; o; o >>= 1) {
            ss += __shfl_xor_sync(0xffffffffu, ss, o);
            sm += __shfl_xor_sync(0xffffffffu, sm, o);
        }
        if (lane == 0) {
            inv[d] = 1.0f / sqrtf(ss);
            pool[d] = sm * (1.0f / HWC);
        }
    }
    __syncthreads();

    for (int h0 = 0; h0 < HWP; h0 += 32) {
        #pragma unroll
        for (int p = 0; p < 8; p++) {
            int d = (t >> 5) + p * 8, hh = t & 31, h = h0 + hh;
            float v = (h < HWC) ? to_tf32(xr[d * HWC + h] * inv[d]) : 0.f;
            xo[d * HWP + h] = v;
            tile[hh][d] = v;
        }
        __syncthreads();
        if (h0 < HWC) {
            #pragma unroll
            for (int p = 0; p < 8; p++) {
                int d = t & 63, hh = (t >> 6) + p * 4, h = h0 + hh;
                // k-interleave perm: group g=d>>3 keeps place; within group,
                // d=g*8+i -> pos g*8+2i ; d=g*8+4+i -> pos g*8+2i+1
                int dp = (d & 0x38) | (((d & 3) << 1) | ((d >> 2) & 1));
                if (h < HWC) xT[(size_t)h * DIMC + dp] = tile[hh][d];
            }
        }
        __syncthreads();
    }
}

// ---------------- prototypes + cosine logits ----------------
__global__ void __launch_bounds__(256) kcos_kernel() {
    const int b = blockIdx.x, t = threadIdx.x;
    __shared__ float proto[WAYS * DIMC];
    __shared__ float pin[WAYS], qin[QN];
    for (int i = t; i < WAYS * DIMC; i += 256) {
        int w = i / DIMC, d = i - w * DIMC;
        float s = 0.f;
        #pragma unroll
        for (int k = 0; k < SHOTS; k++)
            s += g_spool[(b*NSUP + w*SHOTS + k)*DIMC + d];
        proto[i] = s * (1.0f / SHOTS);
    }
    __syncthreads();
    for (int i = t; i < WAYS + QN; i += 256) {
        if (i < WAYS) {
            float ss = 0.f;
            for (int d = 0; d < DIMC; d++) { float v = proto[i*DIMC + d]; ss = fmaf(v, v, ss); }
            pin[i] = 1.0f / sqrtf(ss);
        } else {
            int q = i - WAYS;
            float ss = 0.f;
            for (int d = 0; d < DIMC; d++) { float v = g_qpool[(b*QN + q)*DIMC + d]; ss = fmaf(v, v, ss); }
            qin[q] = 1.0f / sqrtf(ss);
        }
    }
    __syncthreads();
    for (int i = t; i < QN * WAYS; i += 256) {
        int q = i / WAYS, w = i - q * WAYS;
        float dot = 0.f;
        for (int d = 0; d < DIMC; d++)
            dot = fmaf(g_qpool[(b*QN + q)*DIMC + d], proto[w*DIMC + d], dot);
        g_feats[(b*QN + q)*LFE + w] = dot * qin[q] * pin[w];
    }
}

// ---------------- channel-level sim: TF32 mma (R10 winner, 86us) ----------------
__global__ void __launch_bounds__(256) kchan_kernel() {
    const int w = blockIdx.x >> 2, quarter = blockIdx.x & 3;
    const int q = blockIdx.y, b = blockIdx.z;
    __shared__ float As[64][72];
    __shared__ float Bs[80][72];
    const int t = threadIdx.x, lane = t & 31, wid = t >> 5;
    const int wm = wid >> 1, wn = wid & 1;
    const int mrow = wm * 16 + (lane >> 2);
    const int kcol = 2 * (lane & 3);
    const float* __restrict__ qbase = g_qn + (size_t)(b*QN + q) * DIMC * HWP;
    const float* __restrict__ sbase = g_sn + (size_t)(b*NSUP + w*SHOTS) * DIMC * HWP;
    const int jbase = quarter * 80;

    float c[5][4];
    #pragma unroll
    for (int nt = 0; nt < 5; nt++)
        #pragma unroll
        for (int i = 0; i < 4; i++) c[nt][i] = 0.f;

    for (int chunk = 0; chunk < 7; chunk++) {
        const int h0 = chunk * 64;
        __syncthreads();
        for (int idx = t; idx < 512; idx += 256) {
            int m = idx >> 3, g = idx & 7;
            const float* src = qbase + (size_t)m * HWP + h0 + g * 8;
            float4 f0 = *(const float4*)src;
            float4 f1 = *(const float4*)(src + 4);
            float2* dst = (float2*)&As[m][g*8];
            dst[0] = make_float2(f0.x, f1.x);
            dst[1] = make_float2(f0.y, f1.y);
            dst[2] = make_float2(f0.z, f1.z);
            dst[3] = make_float2(f0.w, f1.w);
        }
        for (int idx = t; idx < 640; idx += 256) {
            int jl = idx >> 3, g = idx & 7;
            int j = jbase + jl;
            int shot = j >> 6, dd = j & 63;
            const float* src = sbase + (size_t)(shot*DIMC + dd) * HWP + h0 + g * 8;
            float4 f0 = *(const float4*)src;
            float4 f1 = *(const float4*)(src + 4);
            float2* dst = (float2*)&Bs[jl][g*8];
            dst[0] = make_float2(f0.x, f1.x);
            dst[1] = make_float2(f0.y, f1.y);
            dst[2] = make_float2(f0.z, f1.z);
            dst[3] = make_float2(f0.w, f1.w);
        }
        __syncthreads();
        #pragma unroll
        for (int ks = 0; ks < 8; ks++) {
            uint2 a0 = *(const uint2*)&As[mrow    ][ks*8 + kcol];
            uint2 a1 = *(const uint2*)&As[mrow + 8][ks*8 + kcol];
            #pragma unroll
            for (int nt = 0; nt < 5; nt++) {
                uint2 bb = *(const uint2*)&Bs[wn*40 + nt*8 + (lane>>2)][ks*8 + kcol];
                mma_tf32(c[nt][0], c[nt][1], c[nt][2], c[nt][3],
                         a0.x, a1.x, a0.y, a1.y, bb.x, bb.y);
            }
        }
    }

    float top[2][TOPK];
    #pragma unroll
    for (int r = 0; r < 2; r++)
        #pragma unroll
        for (int k = 0; k < TOPK; k++) top[r][k] = -FLT_MAX;
    #pragma unroll
    for (int nt = 0; nt < 5; nt++) {
        ins5(top[0], c[nt][0]); ins5(top[0], c[nt][1]);
        ins5(top[1], c[nt][2]); ins5(top[1], c[nt][3]);
    }
    #pragma unroll
    for (int off = 1; off <= 2; off <<= 1) {
        #pragma unroll
        for (int r = 0; r < 2; r++) {
            float other[TOPK];
            #pragma unroll
            for (int k = 0; k < TOPK; k++)
                other[k] = __shfl_xor_sync(0xffffffffu, top[r][k], off);
            #pragma unroll
            for (int k = 0; k < TOPK; k++) ins5(top[r], other[k]);
        }
    }

    __syncthreads();
    float (*cand)[10] = (float(*)[10])&As[0][0];
    if ((lane & 3) == 0) {
        #pragma unroll
        for (int r = 0; r < 2; r++) {
            int row = mrow + r * 8;
            #pragma unroll
            for (int k = 0; k < TOPK; k++)
                cand[row][wn*TOPK + k] = top[r][k];
        }
    }
    __syncthreads();
    if (t < DIMC) {
        float t5[TOPK];
        #pragma unroll
        for (int k = 0; k < TOPK; k++) t5[k] = -FLT_MAX;
        #pragma unroll
        for (int i = 0; i < 10; i++) ins5(t5, cand[t][i]);
        float* dst = g_chc + ((size_t)(((b*QN + q)*WAYS + w)*4 + quarter))*DIMC*TOPK + t*TOPK;
        #pragma unroll
        for (int k = 0; k < TOPK; k++) dst[k] = t5[k];
    }
}

// ---------------- merge 4 quarter top-5s per d, sum over d -> sim_l ----------------
__global__ void __launch_bounds__(64) kmerge_kernel() {
    const int bqw = blockIdx.x;
    const int d = threadIdx.x;
    const float* base = g_chc + (size_t)bqw * 4 * DIMC * TOPK;
    float t5[TOPK];
    #pragma unroll
    for (int k = 0; k < TOPK; k++) t5[k] = -FLT_MAX;
    #pragma unroll
    for (int qt = 0; qt < 4; qt++)
        #pragma unroll
        for (int k = 0; k < TOPK; k++)
            ins5(t5, base[(qt*DIMC + d)*TOPK + k]);
    float s = t5[0] + t5[1] + t5[2] + t5[3] + t5[4];
    __shared__ float red[2];
    #pragma unroll
    for (int o = 16; o; o >>= 1) s += __shfl_xor_sync(0xffffffffu, s, o);
    if ((d & 31) == 0) red[d >> 5] = s;
    __syncthreads();
    if (d == 0) {
        int bq = bqw / WAYS, w = bqw % WAYS;
        g_feats[bq*LFE + WAYS + w] = red[0] + red[1];
    }
}

// ---------------- pixel-level sim v2: cp.async double-buffered, A-in-regs ----------------
// Warps: 4 m-groups (16 rows) x 2 n-groups (32 cols). g_qnT/g_snT are perm-interleaved,
// so smem tiles fill verbatim and fragments load as single LDS.64.
__global__ void __launch_bounds__(256) kpix_kernel() {
    const int tile = blockIdx.x;
    const int w = blockIdx.y;
    const int bq = blockIdx.z;
    const int b = bq / QN;
    __shared__ float Bs[2][64][72];
    __shared__ float red[2];
    const int t = threadIdx.x, lane = t & 31, wid = t >> 5;
    const int wm = wid >> 1, wn = wid & 1;
    const int mrow = wm * 16 + (lane >> 2);
    const int kcol = 2 * (lane & 3);
    const int h0 = tile * 64;
    const float* __restrict__ qT = g_qnT + (size_t)bq * HWC * DIMC;
    const float* __restrict__ sT = g_snT + (size_t)(b*NSUP + w*SHOTS) * HWC * DIMC;

    // ---- phase 0: A tile -> Bs[1] via cp.async (verbatim; layout is pre-interleaved)
    #pragma unroll
    for (int i = 0; i < 4; i++) {
        int idx = t + i * 256;
        int m = idx >> 4, seg = idx & 15;
        int h = h0 + m;
        const float* src = qT + (size_t)((h < HWC) ? h : 0) * DIMC + seg * 4;
        cp_async16((uint32_t)__cvta_generic_to_shared(&Bs[1][m][seg*4]), src);
    }
    cp_commit();                                   // group: A
    // ---- phase 0b: B chunk 0 -> Bs[0]
    #pragma unroll
    for (int i = 0; i < 4; i++) {
        int idx = t + i * 256;
        int n = idx >> 4, seg = idx & 15;
        int j = n;                                 // cb = 0
        int shot = j / HWC;
        int h2 = j - shot * HWC;
        const float* src = sT + (size_t)(shot*HWC + h2) * DIMC + seg * 4;
        cp_async16((uint32_t)__cvta_generic_to_shared(&Bs[0][n][seg*4]), src);
    }
    cp_commit();                                   // group: B0
    asm volatile("cp.async.wait_group 1;");        // A done (B0 may be in flight)
    __syncthreads();

    // ---- extract A fragments to registers (1 m16-tile per warp, all 8 k-steps)
    uint2 aF[2][8];
    #pragma unroll
    for (int r = 0; r < 2; r++)
        #pragma unroll
        for (int ks = 0; ks < 8; ks++)
            aF[r][ks] = *(const uint2*)&Bs[1][mrow + 8*r][ks*8 + kcol];
    __syncthreads();                               // Bs[1] free for B chunk 1

    float top[2][TOPK];
    #pragma unroll
    for (int r = 0; r < 2; r++)
        #pragma unroll
        for (int k = 0; k < TOPK; k++) top[r][k] = -FLT_MAX;

    float c[4][4];
    #pragma unroll
    for (int nt = 0; nt < 4; nt++)
        #pragma unroll
        for (int i = 0; i < 4; i++) c[nt][i] = 0.f;

    for (int it = 0; it < 35; it++) {
        const int cb = it * 64;
        const int cur = it & 1;
        __syncthreads();                           // prev iter's reads of buf[cur^1] done
        if (it < 34) {
            const int cbn = cb + 64;
            #pragma unroll
            for (int i = 0; i < 4; i++) {
                int idx = t + i * 256;
                int n = idx >> 4, seg = idx & 15;
                int j = cbn + n;
                int jj = (j < SHW) ? j : 0;        // clamp; garbage masked in epilogue
                int shot = jj / HWC;
                int h2 = jj - shot * HWC;
                const float* src = sT + (size_t)(shot*HWC + h2) * DIMC + seg * 4;
                cp_async16((uint32_t)__cvta_generic_to_shared(&Bs[cur^1][n][seg*4]), src);
            }
            cp_commit();
            asm volatile("cp.async.wait_group 1;");  // B(it) ready
        } else {
            asm volatile("cp.async.wait_group 0;");
        }
        __syncthreads();

        #pragma unroll
        for (int ks = 0; ks < 8; ks++) {
            uint2 f0 = aF[0][ks], f1 = aF[1][ks];
            #pragma unroll
            for (int nt = 0; nt < 4; nt++) {
                uint2 bb = *(const uint2*)&Bs[cur][wn*32 + nt*8 + (lane>>2)][ks*8 + kcol];
                mma_tf32(c[nt][0], c[nt][1], c[nt][2], c[nt][3],
                         f0.x, f1.x, f0.y, f1.y, bb.x, bb.y);
            }
        }

        #pragma unroll
        for (int nt = 0; nt < 4; nt++) {
            int col0 = cb + wn*32 + nt*8 + kcol;
            if (col0 < SHW)     { ins5(top[0], c[nt][0]); ins5(top[1], c[nt][2]); }
            if (col0 + 1 < SHW) { ins5(top[0], c[nt][1]); ins5(top[1], c[nt][3]); }
            c[nt][0] = c[nt][1] = c[nt][2] = c[nt][3] = 0.f;
        }
    }

    // quad merge (lanes sharing a row, covering different columns)
    #pragma unroll
    for (int off = 1; off <= 2; off <<= 1) {
        #pragma unroll
        for (int r = 0; r < 2; r++) {
            float other[TOPK];
            #pragma unroll
            for (int k = 0; k < TOPK; k++)
                other[k] = __shfl_xor_sync(0xffffffffu, top[r][k], off);
            #pragma unroll
            for (int k = 0; k < TOPK; k++) ins5(top[r], other[k]);
        }
    }

    __syncthreads();
    float (*cand)[10] = (float(*)[10])&Bs[0][0][0];
    if ((lane & 3) == 0) {
        #pragma unroll
        for (int r = 0; r < 2; r++) {
            int row = mrow + r * 8;
            #pragma unroll
            for (int k = 0; k < TOPK; k++)
                cand[row][wn*TOPK + k] = top[r][k];
        }
    }
    __syncthreads();

    float rowsum = 0.f;
    if (t < 64) {
        if (h0 + t < HWC) {
            float t5[TOPK];
            #pragma unroll
            for (int k = 0; k < TOPK; k++) t5[k] = -FLT_MAX;
            #pragma unroll
            for (int i = 0; i < 10; i++) ins5(t5, cand[t][i]);
            rowsum = t5[0] + t5[1] + t5[2] + t5[3] + t5[4];
        }
        #pragma unroll
        for (int o = 16; o; o >>= 1) rowsum += __shfl_xor_sync(0xffffffffu, rowsum, o);
        if ((t & 31) == 0) red[t >> 5] = rowsum;
    }
    __syncthreads();
    if (t == 0) g_pix[((size_t)bq*WAYS + w)*NTILE + tile] = red[0] + red[1];
}

// ---------------- BN (batch stats) + dilated conv ----------------
__global__ void __launch_bounds__(256) kfin_kernel(const float* __restrict__ gamma,
                                                   const float* __restrict__ beta,
                                                   const float* __restrict__ cw,
                                                   float* __restrict__ out) {
    const int b = blockIdx.x;
    __shared__ float f[QN][LFE];
    __shared__ float mu[LFE], iv[LFE];
    const int t = threadIdx.x;
    for (int i = t; i < QN * WAYS; i += 256) {
        int q = i / WAYS, w = i - q * WAYS;
        const float* fr = &g_feats[(b*QN + q)*LFE];
        f[q][w]     = fr[w];
        f[q][5 + w] = fr[5 + w];
        float s = 0.f;
        #pragma unroll
        for (int j = 0; j < NTILE; j++)
            s += g_pix[((size_t)(b*QN + q)*WAYS + w)*NTILE + j];
        f[q][10 + w] = s;
    }
    __syncthreads();
    if (t < LFE) {
        float m = 0.f;
        for (int q = 0; q < QN; q++) m += f[q][t];
        m *= (1.0f / QN);
        float v = 0.f;
        for (int q = 0; q < QN; q++) { float d = f[q][t] - m; v = fmaf(d, d, v); }
        v *= (1.0f / QN);
        mu[t] = m;
        iv[t] = 1.0f / sqrtf(v + 1e-5f);
    }
    __syncthreads();
    float w0 = cw[0], w1 = cw[1], w2 = cw[2];
    for (int i = t; i < QN * WAYS; i += 256) {
        int q = i / WAYS, c = i - q * WAYS;
        float b0 = (f[q][c]      - mu[c])      * iv[c]      * gamma[c]      + beta[c];
        float b1 = (f[q][c + 5]  - mu[c + 5])  * iv[c + 5]  * gamma[c + 5]  + beta[c + 5];
        float b2 = (f[q][c + 10] - mu[c + 10]) * iv[c + 10] * gamma[c + 10] + beta[c + 10];
        out[(b*QN + q)*WAYS + c] = w0*b0 + w1*b1 + w2*b2;
    }
}

// ---------------- launch ----------------
extern "C" void kernel_launch(void* const* d_in, const int* in_sizes, int n_in,
                              void* d_out, int out_size) {
    const float* q     = (const float*)d_in[0];
    const float* s     = (const float*)d_in[1];
    const float* gamma = (const float*)d_in[2];
    const float* beta  = (const float*)d_in[3];
    const float* cw    = (const float*)d_in[4];
    float* out = (float*)d_out;

    knorm_kernel<0><<<BB*QN, 256>>>(q);
    knorm_kernel<1><<<BB*NSUP, 256>>>(s);
    kcos_kernel<<<BB, 256>>>();
    kchan_kernel<<<dim3(20, QN, BB), 256>>>();
    kpix_kernel<<<dim3(NTILE, WAYS, BB*QN), 256>>>();
    kmerge_kernel<<<BB*QN*WAYS, 64>>>();
    kfin_kernel<<<BB, 256>>>(gamma, beta, cw, out);
}

// round 12
// speedup vs baseline: 4.9669x; 1.3485x over previous
#include <cuda_runtime.h>
#include <cuda_fp16.h>
#include <math.h>
#include <float.h>
#include <stdint.h>

#define BB   2
#define QN   30
#define WAYS 5
#define SHOTS 5
#define TOPK 5
#define DIMC 64
#define HWC  441
#define HWP  448
#define NSUP (WAYS*SHOTS)
#define LFE  15
#define SHW  (SHOTS*HWC)   // 2205
#define NTILE 7

// ---------------- scratch ----------------
__device__ __align__(16) __half g_qnH [BB*QN*DIMC*HWP];    // [n][d][perm16(h)] fp16, h zero-padded (kchan)
__device__ __align__(16) __half g_snH [BB*NSUP*DIMC*HWP];
__device__ __align__(16) __half g_qnTH[BB*QN*HWC*DIMC];    // [n][h][perm16(d)] fp16 (kpix)
__device__ __align__(16) __half g_snTH[BB*NSUP*HWC*DIMC];
__device__ float g_qpool[BB*QN*DIMC];
__device__ float g_spool[BB*NSUP*DIMC];
__device__ float g_feats[BB*QN*LFE];
__device__ float g_pix[BB*QN*WAYS*NTILE];
__device__ float g_chc[BB*QN*WAYS*4*DIMC*TOPK];

// fp16 k-perm within a 16-group: pos = 4*((k>>1)&3) + 2*((k>>3)&1) + (k&1)
// -> positions [4c+0,4c+1] hold k={2c,2c+1}; [4c+2,4c+3] hold k={2c+8,2c+9}
__device__ __forceinline__ int perm16(int k) {
    return 4*((k >> 1) & 3) + 2*((k >> 3) & 1) + (k & 1);
}

__device__ __forceinline__ void mma_f16(float &c0, float &c1, float &c2, float &c3,
                                        uint32_t a0, uint32_t a1, uint32_t a2, uint32_t a3,
                                        uint32_t b0, uint32_t b1) {
    asm("mma.sync.aligned.m16n8k16.row.col.f32.f16.f16.f32 "
        "{%0,%1,%2,%3}, {%4,%5,%6,%7}, {%8,%9}, {%0,%1,%2,%3};"
        : "+f"(c0), "+f"(c1), "+f"(c2), "+f"(c3)
        : "r"(a0), "r"(a1), "r"(a2), "r"(a3), "r"(b0), "r"(b1));
}
__device__ __forceinline__ void cp_async16(uint32_t dst, const void* src) {
    asm volatile("cp.async.cg.shared.global [%0], [%1], 16;" :: "r"(dst), "l"(src));
}
__device__ __forceinline__ void cp_commit() {
    asm volatile("cp.async.commit_group;");
}

__device__ __forceinline__ void ins5(float (&t)[TOPK], float v) {
    if (v > t[TOPK-1]) {
        float x = v;
        #pragma unroll
        for (int i = 0; i < TOPK; i++) {
            float hi = fmaxf(t[i], x);
            x = fminf(t[i], x);
            t[i] = hi;
        }
    }
}

// ---------------- L2-normalize + mean-pool + fp16 perm writes ----------------
template<int IS_S>
__global__ void __launch_bounds__(256) knorm_kernel(const float* __restrict__ x) {
    const int n = blockIdx.x;
    __half* __restrict__ xo = (IS_S ? g_snH  : g_qnH)  + (size_t)n * DIMC * HWP;
    __half* __restrict__ xT = (IS_S ? g_snTH : g_qnTH) + (size_t)n * HWC * DIMC;
    float* __restrict__ pool = (IS_S ? g_spool : g_qpool) + n * DIMC;
    const float* __restrict__ xr = x + (size_t)n * DIMC * HWC;
    __shared__ float inv[DIMC];
    __shared__ float tile[32][65];
    const int t = threadIdx.x, warp = t >> 5, lane = t & 31;

    for (int d = warp; d < DIMC; d += 8) {
        const float* row = xr + d * HWC;
        float ss = 0.f, sm = 0.f;
        for (int h = lane; h < HWC; h += 32) {
            float v = row[h];
            ss = fmaf(v, v, ss);
            sm += v;
        }
        #pragma unroll
        for (int o = 16; o; o >>= 1) {
            ss += __shfl_xor_sync(0xffffffffu, ss, o);
            sm += __shfl_xor_sync(0xffffffffu, sm, o);
        }
        if (lane == 0) {
            inv[d] = 1.0f / sqrtf(ss);
            pool[d] = sm * (1.0f / HWC);
        }
    }
    __syncthreads();

    for (int h0 = 0; h0 < HWP; h0 += 32) {
        #pragma unroll
        for (int p = 0; p < 8; p++) {
            int d = (t >> 5) + p * 8, hh = t & 31, h = h0 + hh;
            float v = (h < HWC) ? xr[d * HWC + h] * inv[d] : 0.f;
            int ph = (hh & 16) | perm16(hh & 15);          // h-perm within 16-group
            xo[d * HWP + h0 + ph] = __float2half_rn(v);
            tile[hh][d] = v;
        }
        __syncthreads();
        if (h0 < HWC) {
            #pragma unroll
            for (int p = 0; p < 8; p++) {
                int d = t & 63, hh = (t >> 6) + p * 4, h = h0 + hh;
                int dp = (d & 48) | perm16(d & 15);        // d-perm within 16-group
                if (h < HWC) xT[(size_t)h * DIMC + dp] = __float2half_rn(tile[hh][d]);
            }
        }
        __syncthreads();
    }
}

// ---------------- prototypes + cosine logits (fp32 pools) ----------------
__global__ void __launch_bounds__(256) kcos_kernel() {
    const int b = blockIdx.x, t = threadIdx.x;
    __shared__ float proto[WAYS * DIMC];
    __shared__ float pin[WAYS], qin[QN];
    for (int i = t; i < WAYS * DIMC; i += 256) {
        int w = i / DIMC, d = i - w * DIMC;
        float s = 0.f;
        #pragma unroll
        for (int k = 0; k < SHOTS; k++)
            s += g_spool[(b*NSUP + w*SHOTS + k)*DIMC + d];
        proto[i] = s * (1.0f / SHOTS);
    }
    __syncthreads();
    for (int i = t; i < WAYS + QN; i += 256) {
        if (i < WAYS) {
            float ss = 0.f;
            for (int d = 0; d < DIMC; d++) { float v = proto[i*DIMC + d]; ss = fmaf(v, v, ss); }
            pin[i] = 1.0f / sqrtf(ss);
        } else {
            int q = i - WAYS;
            float ss = 0.f;
            for (int d = 0; d < DIMC; d++) { float v = g_qpool[(b*QN + q)*DIMC + d]; ss = fmaf(v, v, ss); }
            qin[q] = 1.0f / sqrtf(ss);
        }
    }
    __syncthreads();
    for (int i = t; i < QN * WAYS; i += 256) {
        int q = i / WAYS, w = i - q * WAYS;
        float dot = 0.f;
        for (int d = 0; d < DIMC; d++)
            dot = fmaf(g_qpool[(b*QN + q)*DIMC + d], proto[w*DIMC + d], dot);
        g_feats[(b*QN + q)*LFE + w] = dot * qin[q] * pin[w];
    }
}

// ---------------- channel-level sim v2: fp16 mma, cp.async double-buffered ----------------
// C[64d x 80j] per quarter, K=448 (7 chunks of 64h = 4 k16-steps each).
// Warps: 4 m-groups x 2 n-groups (40 j each). A rows 0-63, B rows 64-143 of AB.
__global__ void __launch_bounds__(256) kchan_kernel() {
    const int w = blockIdx.x >> 2, quarter = blockIdx.x & 3;
    const int q = blockIdx.y, b = blockIdx.z;
    __shared__ __align__(16) __half AB[2][144][72];
    const int t = threadIdx.x, lane = t & 31, wid = t >> 5;
    const int wm = wid >> 1, wn = wid & 1;
    const int mrow = wm * 16 + (lane >> 2);
    const int fcol = 4 * (lane & 3);                 // f16 offset of thread's k-quad
    const __half* __restrict__ qbase = g_qnH + (size_t)(b*QN + q) * DIMC * HWP;
    const __half* __restrict__ sbase = g_snH + (size_t)(b*NSUP + w*SHOTS) * DIMC * HWP;
    const int jbase = quarter * 80;

    float c[5][4];
    #pragma unroll
    for (int nt = 0; nt < 5; nt++)
        #pragma unroll
        for (int i = 0; i < 4; i++) c[nt][i] = 0.f;

    // fill: 64 A rows (8 segs) + 80 B rows (8 segs) = 1152 x 16B
    auto fill = [&](int buf, int h0) {
        for (int idx = t; idx < 1152; idx += 256) {
            const __half* src;
            int row, seg;
            if (idx < 512) {
                row = idx >> 3; seg = idx & 7;
                src = qbase + (size_t)row * HWP + h0 + seg * 8;
            } else {
                int r = idx - 512;
                int jl = r >> 3; seg = r & 7;
                int j = jbase + jl;
                int shot = j >> 6, dd = j & 63;
                row = 64 + jl;
                src = sbase + (size_t)(shot*DIMC + dd) * HWP + h0 + seg * 8;
            }
            cp_async16((uint32_t)__cvta_generic_to_shared(&AB[buf][row][seg*8]), src);
        }
        cp_commit();
    };

    fill(0, 0);
    for (int it = 0; it < 7; it++) {
        const int cur = it & 1;
        __syncthreads();                              // prev reads of buf cur^1 done
        if (it < 6) {
            fill(cur ^ 1, (it + 1) * 64);
            asm volatile("cp.async.wait_group 1;");   // chunk(it) ready
        } else {
            asm volatile("cp.async.wait_group 0;");
        }
        __syncthreads();
        #pragma unroll
        for (int ks = 0; ks < 4; ks++) {
            uint2 alo = *(const uint2*)&AB[cur][mrow    ][ks*16 + fcol];
            uint2 ahi = *(const uint2*)&AB[cur][mrow + 8][ks*16 + fcol];
            #pragma unroll
            for (int nt = 0; nt < 5; nt++) {
                uint2 bb = *(const uint2*)&AB[cur][64 + wn*40 + nt*8 + (lane>>2)][ks*16 + fcol];
                mma_f16(c[nt][0], c[nt][1], c[nt][2], c[nt][3],
                        alo.x, ahi.x, alo.y, ahi.y, bb.x, bb.y);
            }
        }
    }

    float top[2][TOPK];
    #pragma unroll
    for (int r = 0; r < 2; r++)
        #pragma unroll
        for (int k = 0; k < TOPK; k++) top[r][k] = -FLT_MAX;
    #pragma unroll
    for (int nt = 0; nt < 5; nt++) {
        ins5(top[0], c[nt][0]); ins5(top[0], c[nt][1]);
        ins5(top[1], c[nt][2]); ins5(top[1], c[nt][3]);
    }
    #pragma unroll
    for (int off = 1; off <= 2; off <<= 1) {
        #pragma unroll
        for (int r = 0; r < 2; r++) {
            float other[TOPK];
            #pragma unroll
            for (int k = 0; k < TOPK; k++)
                other[k] = __shfl_xor_sync(0xffffffffu, top[r][k], off);
            #pragma unroll
            for (int k = 0; k < TOPK; k++) ins5(top[r], other[k]);
        }
    }

    __syncthreads();
    float (*cand)[10] = (float(*)[10])&AB[0][0][0];
    if ((lane & 3) == 0) {
        #pragma unroll
        for (int r = 0; r < 2; r++) {
            int row = mrow + r * 8;
            #pragma unroll
            for (int k = 0; k < TOPK; k++)
                cand[row][wn*TOPK + k] = top[r][k];
        }
    }
    __syncthreads();
    if (t < DIMC) {
        float t5[TOPK];
        #pragma unroll
        for (int k = 0; k < TOPK; k++) t5[k] = -FLT_MAX;
        #pragma unroll
        for (int i = 0; i < 10; i++) ins5(t5, cand[t][i]);
        float* dst = g_chc + ((size_t)(((b*QN + q)*WAYS + w)*4 + quarter))*DIMC*TOPK + t*TOPK;
        #pragma unroll
        for (int k = 0; k < TOPK; k++) dst[k] = t5[k];
    }
}

// ---------------- merge 4 quarter top-5s per d, sum over d -> sim_l ----------------
__global__ void __launch_bounds__(64) kmerge_kernel() {
    const int bqw = blockIdx.x;
    const int d = threadIdx.x;
    const float* base = g_chc + (size_t)bqw * 4 * DIMC * TOPK;
    float t5[TOPK];
    #pragma unroll
    for (int k = 0; k < TOPK; k++) t5[k] = -FLT_MAX;
    #pragma unroll
    for (int qt = 0; qt < 4; qt++)
        #pragma unroll
        for (int k = 0; k < TOPK; k++)
            ins5(t5, base[(qt*DIMC + d)*TOPK + k]);
    float s = t5[0] + t5[1] + t5[2] + t5[3] + t5[4];
    __shared__ float red[2];
    #pragma unroll
    for (int o = 16; o; o >>= 1) s += __shfl_xor_sync(0xffffffffu, s, o);
    if ((d & 31) == 0) red[d >> 5] = s;
    __syncthreads();
    if (d == 0) {
        int bq = bqw / WAYS, w = bqw % WAYS;
        g_feats[bq*LFE + WAYS + w] = red[0] + red[1];
    }
}

// ---------------- pixel-level sim v3: fp16 mma, cp.async double-buffered, A-in-regs ----------------
__global__ void __launch_bounds__(256) kpix_kernel() {
    const int tile = blockIdx.x;
    const int w = blockIdx.y;
    const int bq = blockIdx.z;
    const int b = bq / QN;
    __shared__ __align__(16) __half Bs[2][64][72];
    __shared__ float red[2];
    const int t = threadIdx.x, lane = t & 31, wid = t >> 5;
    const int wm = wid >> 1, wn = wid & 1;
    const int mrow = wm * 16 + (lane >> 2);
    const int fcol = 4 * (lane & 3);
    const int h0 = tile * 64;
    const __half* __restrict__ qT = g_qnTH + (size_t)bq * HWC * DIMC;
    const __half* __restrict__ sT = g_snTH + (size_t)(b*NSUP + w*SHOTS) * HWC * DIMC;

    // A tile -> Bs[1] (verbatim; perm baked in gmem). 64 rows x 8 segs = 512 ops.
    #pragma unroll
    for (int i = 0; i < 2; i++) {
        int idx = t + i * 256;
        int m = idx >> 3, seg = idx & 7;
        int h = h0 + m;
        const __half* src = qT + (size_t)((h < HWC) ? h : 0) * DIMC + seg * 8;
        cp_async16((uint32_t)__cvta_generic_to_shared(&Bs[1][m][seg*8]), src);
    }
    cp_commit();                                    // group: A
    // B chunk 0 -> Bs[0]
    #pragma unroll
    for (int i = 0; i < 2; i++) {
        int idx = t + i * 256;
        int n = idx >> 3, seg = idx & 7;
        int shot = n / HWC;                         // cb = 0 -> j = n < 64, shot = 0
        int h2 = n - shot * HWC;
        const __half* src = sT + (size_t)(shot*HWC + h2) * DIMC + seg * 8;
        cp_async16((uint32_t)__cvta_generic_to_shared(&Bs[0][n][seg*8]), src);
    }
    cp_commit();                                    // group: B0
    asm volatile("cp.async.wait_group 1;");         // A done
    __syncthreads();

    // A fragments to registers: 4 k16-steps, rows mrow & mrow+8
    uint2 aF[2][4];
    #pragma unroll
    for (int r = 0; r < 2; r++)
        #pragma unroll
        for (int ks = 0; ks < 4; ks++)
            aF[r][ks] = *(const uint2*)&Bs[1][mrow + 8*r][ks*16 + fcol];
    __syncthreads();                                // Bs[1] free

    float top[2][TOPK];
    #pragma unroll
    for (int r = 0; r < 2; r++)
        #pragma unroll
        for (int k = 0; k < TOPK; k++) top[r][k] = -FLT_MAX;

    float c[4][4];
    #pragma unroll
    for (int nt = 0; nt < 4; nt++)
        #pragma unroll
        for (int i = 0; i < 4; i++) c[nt][i] = 0.f;

    for (int it = 0; it < 35; it++) {
        const int cb = it * 64;
        const int cur = it & 1;
        __syncthreads();
        if (it < 34) {
            const int cbn = cb + 64;
            #pragma unroll
            for (int i = 0; i < 2; i++) {
                int idx = t + i * 256;
                int n = idx >> 3, seg = idx & 7;
                int j = cbn + n;
                int jj = (j < SHW) ? j : 0;
                int shot = jj / HWC;
                int h2 = jj - shot * HWC;
                const __half* src = sT + (size_t)(shot*HWC + h2) * DIMC + seg * 8;
                cp_async16((uint32_t)__cvta_generic_to_shared(&Bs[cur^1][n][seg*8]), src);
            }
            cp_commit();
            asm volatile("cp.async.wait_group 1;");
        } else {
            asm volatile("cp.async.wait_group 0;");
        }
        __syncthreads();

        #pragma unroll
        for (int ks = 0; ks < 4; ks++) {
            uint2 f0 = aF[0][ks], f1 = aF[1][ks];
            #pragma unroll
            for (int nt = 0; nt < 4; nt++) {
                uint2 bb = *(const uint2*)&Bs[cur][wn*32 + nt*8 + (lane>>2)][ks*16 + fcol];
                mma_f16(c[nt][0], c[nt][1], c[nt][2], c[nt][3],
                        f0.x, f1.x, f0.y, f1.y, bb.x, bb.y);
            }
        }

        #pragma unroll
        for (int nt = 0; nt < 4; nt++) {
            int col0 = cb + wn*32 + nt*8 + 2*(lane & 3);
            if (col0 < SHW)     { ins5(top[0], c[nt][0]); ins5(top[1], c[nt][2]); }
            if (col0 + 1 < SHW) { ins5(top[0], c[nt][1]); ins5(top[1], c[nt][3]); }
            c[nt][0] = c[nt][1] = c[nt][2] = c[nt][3] = 0.f;
        }
    }

    #pragma unroll
    for (int off = 1; off <= 2; off <<= 1) {
        #pragma unroll
        for (int r = 0; r < 2; r++) {
            float other[TOPK];
            #pragma unroll
            for (int k = 0; k < TOPK; k++)
                other[k] = __shfl_xor_sync(0xffffffffu, top[r][k], off);
            #pragma unroll
            for (int k = 0; k < TOPK; k++) ins5(top[r], other[k]);
        }
    }

    __syncthreads();
    float (*cand)[10] = (float(*)[10])&Bs[0][0][0];
    if ((lane & 3) == 0) {
        #pragma unroll
        for (int r = 0; r < 2; r++) {
            int row = mrow + r * 8;
            #pragma unroll
            for (int k = 0; k < TOPK; k++)
                cand[row][wn*TOPK + k] = top[r][k];
        }
    }
    __syncthreads();

    float rowsum = 0.f;
    if (t < 64) {
        if (h0 + t < HWC) {
            float t5[TOPK];
            #pragma unroll
            for (int k = 0; k < TOPK; k++) t5[k] = -FLT_MAX;
            #pragma unroll
            for (int i = 0; i < 10; i++) ins5(t5, cand[t][i]);
            rowsum = t5[0] + t5[1] + t5[2] + t5[3] + t5[4];
        }
        #pragma unroll
        for (int o = 16; o; o >>= 1) rowsum += __shfl_xor_sync(0xffffffffu, rowsum, o);
        if ((t & 31) == 0) red[t >> 5] = rowsum;
    }
    __syncthreads();
    if (t == 0) g_pix[((size_t)bq*WAYS + w)*NTILE + tile] = red[0] + red[1];
}

// ---------------- BN (batch stats) + dilated conv ----------------
__global__ void __launch_bounds__(256) kfin_kernel(const float* __restrict__ gamma,
                                                   const float* __restrict__ beta,
                                                   const float* __restrict__ cw,
                                                   float* __restrict__ out) {
    const int b = blockIdx.x;
    __shared__ float f[QN][LFE];
    __shared__ float mu[LFE], iv[LFE];
    const int t = threadIdx.x;
    for (int i = t; i < QN * WAYS; i += 256) {
        int q = i / WAYS, w = i - q * WAYS;
        const float* fr = &g_feats[(b*QN + q)*LFE];
        f[q][w]     = fr[w];
        f[q][5 + w] = fr[5 + w];
        float s = 0.f;
        #pragma unroll
        for (int j = 0; j < NTILE; j++)
            s += g_pix[((size_t)(b*QN + q)*WAYS + w)*NTILE + j];
        f[q][10 + w] = s;
    }
    __syncthreads();
    if (t < LFE) {
        float m = 0.f;
        for (int q = 0; q < QN; q++) m += f[q][t];
        m *= (1.0f / QN);
        float v = 0.f;
        for (int q = 0; q < QN; q++) { float d = f[q][t] - m; v = fmaf(d, d, v); }
        v *= (1.0f / QN);
        mu[t] = m;
        iv[t] = 1.0f / sqrtf(v + 1e-5f);
    }
    __syncthreads();
    float w0 = cw[0], w1 = cw[1], w2 = cw[2];
    for (int i = t; i < QN * WAYS; i += 256) {
        int q = i / WAYS, c = i - q * WAYS;
        float b0 = (f[q][c]      - mu[c])      * iv[c]      * gamma[c]      + beta[c];
        float b1 = (f[q][c + 5]  - mu[c + 5])  * iv[c + 5]  * gamma[c + 5]  + beta[c + 5];
        float b2 = (f[q][c + 10] - mu[c + 10]) * iv[c + 10] * gamma[c + 10] + beta[c + 10];
        out[(b*QN + q)*WAYS + c] = w0*b0 + w1*b1 + w2*b2;
    }
}

// ---------------- launch ----------------
extern "C" void kernel_launch(void* const* d_in, const int* in_sizes, int n_in,
                              void* d_out, int out_size) {
    const float* q     = (const float*)d_in[0];
    const float* s     = (const float*)d_in[1];
    const float* gamma = (const float*)d_in[2];
    const float* beta  = (const float*)d_in[3];
    const float* cw    = (const float*)d_in[4];
    float* out = (float*)d_out;

    knorm_kernel<0><<<BB*QN, 256>>>(q);
    knorm_kernel<1><<<BB*NSUP, 256>>>(s);
    kcos_kernel<<<BB, 256>>>();
    kchan_kernel<<<dim3(20, QN, BB), 256>>>();
    kpix_kernel<<<dim3(NTILE, WAYS, BB*QN), 256>>>();
    kmerge_kernel<<<BB*QN*WAYS, 64>>>();
    kfin_kernel<<<BB, 256>>>(gamma, beta, cw, out);
}

// round 13
// speedup vs baseline: 4.9953x; 1.0057x over previous
#include <cuda_runtime.h>
#include <cuda_fp16.h>
#include <math.h>
#include <float.h>
#include <stdint.h>

#define BB   2
#define QN   30
#define WAYS 5
#define SHOTS 5
#define TOPK 5
#define DIMC 64
#define HWC  441
#define HWP  448
#define NSUP (WAYS*SHOTS)
#define LFE  15
#define SHW  (SHOTS*HWC)   // 2205
#define NTILE 7

// ---------------- scratch ----------------
__device__ __align__(16) __half g_qnH [BB*QN*DIMC*HWP];    // [n][d][perm16(h)] fp16 (kchan)
__device__ __align__(16) __half g_snH [BB*NSUP*DIMC*HWP];
__device__ __align__(16) __half g_qnTH[BB*QN*HWC*DIMC];    // [n][h][perm64(d)] fp16 (kpix)
__device__ __align__(16) __half g_snTH[BB*NSUP*HWC*DIMC];
__device__ float g_qpool[BB*QN*DIMC];
__device__ float g_spool[BB*NSUP*DIMC];
__device__ float g_feats[BB*QN*LFE];
__device__ float g_pix[BB*QN*WAYS*NTILE];
__device__ float g_chc[BB*QN*WAYS*4*DIMC*TOPK];

// fp16 k-perm within one 16-group (kchan layout):
// pos = 4*((k>>1)&3) + 2*((k>>3)&1) + (k&1)
__device__ __forceinline__ int perm16(int k) {
    return 4*((k >> 1) & 3) + 2*((k >> 3) & 1) + (k & 1);
}
// kpix 64-wide perm with ks-PAIRING: for k in [0,64), ks=k>>4, p=ks>>1, e=ks&1, r=k&15:
// pos = 32p + 8*((r>>1)&3) + 4e + (2*((r>>3)&1) + (r&1))
// -> thread c's 16B at [32p + 8c] = [evenquad(ks=2p,c) | oddquad(ks=2p+1,c)]
__device__ __forceinline__ int perm64(int k) {
    int ks = k >> 4, p = ks >> 1, e = ks & 1, r = k & 15;
    return 32*p + 8*((r >> 1) & 3) + 4*e + (2*((r >> 3) & 1) + (r & 1));
}

__device__ __forceinline__ void mma_f16(float &c0, float &c1, float &c2, float &c3,
                                        uint32_t a0, uint32_t a1, uint32_t a2, uint32_t a3,
                                        uint32_t b0, uint32_t b1) {
    asm("mma.sync.aligned.m16n8k16.row.col.f32.f16.f16.f32 "
        "{%0,%1,%2,%3}, {%4,%5,%6,%7}, {%8,%9}, {%0,%1,%2,%3};"
        : "+f"(c0), "+f"(c1), "+f"(c2), "+f"(c3)
        : "r"(a0), "r"(a1), "r"(a2), "r"(a3), "r"(b0), "r"(b1));
}
// zero-start variant: d = a*b + 0 (kills per-chunk accumulator zeroing)
__device__ __forceinline__ void mma_f16_z(float &c0, float &c1, float &c2, float &c3,
                                          uint32_t a0, uint32_t a1, uint32_t a2, uint32_t a3,
                                          uint32_t b0, uint32_t b1) {
    asm("mma.sync.aligned.m16n8k16.row.col.f32.f16.f16.f32 "
        "{%0,%1,%2,%3}, {%4,%5,%6,%7}, {%8,%9}, {%10,%11,%12,%13};"
        : "=f"(c0), "=f"(c1), "=f"(c2), "=f"(c3)
        : "r"(a0), "r"(a1), "r"(a2), "r"(a3), "r"(b0), "r"(b1),
          "f"(0.f), "f"(0.f), "f"(0.f), "f"(0.f));
}
__device__ __forceinline__ void cp_async16(uint32_t dst, const void* src) {
    asm volatile("cp.async.cg.shared.global [%0], [%1], 16;" :: "r"(dst), "l"(src));
}
__device__ __forceinline__ void cp_commit() {
    asm volatile("cp.async.commit_group;");
}

__device__ __forceinline__ void ins5(float (&t)[TOPK], float v) {
    if (v > t[TOPK-1]) {
        float x = v;
        #pragma unroll
        for (int i = 0; i < TOPK; i++) {
            float hi = fmaxf(t[i], x);
            x = fminf(t[i], x);
            t[i] = hi;
        }
    }
}

// ---------------- L2-normalize + mean-pool + fp16 perm writes ----------------
template<int IS_S>
__global__ void __launch_bounds__(256) knorm_kernel(const float* __restrict__ x) {
    const int n = blockIdx.x;
    __half* __restrict__ xo = (IS_S ? g_snH  : g_qnH)  + (size_t)n * DIMC * HWP;
    __half* __restrict__ xT = (IS_S ? g_snTH : g_qnTH) + (size_t)n * HWC * DIMC;
    float* __restrict__ pool = (IS_S ? g_spool : g_qpool) + n * DIMC;
    const float* __restrict__ xr = x + (size_t)n * DIMC * HWC;
    __shared__ float inv[DIMC];
    __shared__ float tile[32][65];
    const int t = threadIdx.x, warp = t >> 5, lane = t & 31;

    for (int d = warp; d < DIMC; d += 8) {
        const float* row = xr + d * HWC;
        float ss = 0.f, sm = 0.f;
        for (int h = lane; h < HWC; h += 32) {
            float v = row[h];
            ss = fmaf(v, v, ss);
            sm += v;
        }
        #pragma unroll
        for (int o = 16; o; o >>= 1) {
            ss += __shfl_xor_sync(0xffffffffu, ss, o);
            sm += __shfl_xor_sync(0xffffffffu, sm, o);
        }
        if (lane == 0) {
            inv[d] = 1.0f / sqrtf(ss);
            pool[d] = sm * (1.0f / HWC);
        }
    }
    __syncthreads();

    for (int h0 = 0; h0 < HWP; h0 += 32) {
        #pragma unroll
        for (int p = 0; p < 8; p++) {
            int d = (t >> 5) + p * 8, hh = t & 31, h = h0 + hh;
            float v = (h < HWC) ? xr[d * HWC + h] * inv[d] : 0.f;
            int ph = (hh & 16) | perm16(hh & 15);
            xo[d * HWP + h0 + ph] = __float2half_rn(v);
            tile[hh][d] = v;
        }
        __syncthreads();
        if (h0 < HWC) {
            #pragma unroll
            for (int p = 0; p < 8; p++) {
                int d = t & 63, hh = (t >> 6) + p * 4, h = h0 + hh;
                if (h < HWC) xT[(size_t)h * DIMC + perm64(d)] = __float2half_rn(tile[hh][d]);
            }
        }
        __syncthreads();
    }
}

// ---------------- prototypes + cosine logits (fp32 pools) ----------------
__global__ void __launch_bounds__(256) kcos_kernel() {
    const int b = blockIdx.x, t = threadIdx.x;
    __shared__ float proto[WAYS * DIMC];
    __shared__ float pin[WAYS], qin[QN];
    for (int i = t; i < WAYS * DIMC; i += 256) {
        int w = i / DIMC, d = i - w * DIMC;
        float s = 0.f;
        #pragma unroll
        for (int k = 0; k < SHOTS; k++)
            s += g_spool[(b*NSUP + w*SHOTS + k)*DIMC + d];
        proto[i] = s * (1.0f / SHOTS);
    }
    __syncthreads();
    for (int i = t; i < WAYS + QN; i += 256) {
        if (i < WAYS) {
            float ss = 0.f;
            for (int d = 0; d < DIMC; d++) { float v = proto[i*DIMC + d]; ss = fmaf(v, v, ss); }
            pin[i] = 1.0f / sqrtf(ss);
        } else {
            int q = i - WAYS;
            float ss = 0.f;
            for (int d = 0; d < DIMC; d++) { float v = g_qpool[(b*QN + q)*DIMC + d]; ss = fmaf(v, v, ss); }
            qin[q] = 1.0f / sqrtf(ss);
        }
    }
    __syncthreads();
    for (int i = t; i < QN * WAYS; i += 256) {
        int q = i / WAYS, w = i - q * WAYS;
        float dot = 0.f;
        for (int d = 0; d < DIMC; d++)
            dot = fmaf(g_qpool[(b*QN + q)*DIMC + d], proto[w*DIMC + d], dot);
        g_feats[(b*QN + q)*LFE + w] = dot * qin[q] * pin[w];
    }
}

// ---------------- channel-level sim (R12 winner, 49.7us) ----------------
__global__ void __launch_bounds__(256) kchan_kernel() {
    const int w = blockIdx.x >> 2, quarter = blockIdx.x & 3;
    const int q = blockIdx.y, b = blockIdx.z;
    __shared__ __align__(16) __half AB[2][144][72];
    const int t = threadIdx.x, lane = t & 31, wid = t >> 5;
    const int wm = wid >> 1, wn = wid & 1;
    const int mrow = wm * 16 + (lane >> 2);
    const int fcol = 4 * (lane & 3);
    const __half* __restrict__ qbase = g_qnH + (size_t)(b*QN + q) * DIMC * HWP;
    const __half* __restrict__ sbase = g_snH + (size_t)(b*NSUP + w*SHOTS) * DIMC * HWP;
    const int jbase = quarter * 80;

    float c[5][4];
    #pragma unroll
    for (int nt = 0; nt < 5; nt++)
        #pragma unroll
        for (int i = 0; i < 4; i++) c[nt][i] = 0.f;

    auto fill = [&](int buf, int h0) {
        for (int idx = t; idx < 1152; idx += 256) {
            const __half* src;
            int row, seg;
            if (idx < 512) {
                row = idx >> 3; seg = idx & 7;
                src = qbase + (size_t)row * HWP + h0 + seg * 8;
            } else {
                int r = idx - 512;
                int jl = r >> 3; seg = r & 7;
                int j = jbase + jl;
                int shot = j >> 6, dd = j & 63;
                row = 64 + jl;
                src = sbase + (size_t)(shot*DIMC + dd) * HWP + h0 + seg * 8;
            }
            cp_async16((uint32_t)__cvta_generic_to_shared(&AB[buf][row][seg*8]), src);
        }
        cp_commit();
    };

    fill(0, 0);
    for (int it = 0; it < 7; it++) {
        const int cur = it & 1;
        __syncthreads();
        if (it < 6) {
            fill(cur ^ 1, (it + 1) * 64);
            asm volatile("cp.async.wait_group 1;");
        } else {
            asm volatile("cp.async.wait_group 0;");
        }
        __syncthreads();
        #pragma unroll
        for (int ks = 0; ks < 4; ks++) {
            uint2 alo = *(const uint2*)&AB[cur][mrow    ][ks*16 + fcol];
            uint2 ahi = *(const uint2*)&AB[cur][mrow + 8][ks*16 + fcol];
            #pragma unroll
            for (int nt = 0; nt < 5; nt++) {
                uint2 bb = *(const uint2*)&AB[cur][64 + wn*40 + nt*8 + (lane>>2)][ks*16 + fcol];
                mma_f16(c[nt][0], c[nt][1], c[nt][2], c[nt][3],
                        alo.x, ahi.x, alo.y, ahi.y, bb.x, bb.y);
            }
        }
    }

    float top[2][TOPK];
    #pragma unroll
    for (int r = 0; r < 2; r++)
        #pragma unroll
        for (int k = 0; k < TOPK; k++) top[r][k] = -FLT_MAX;
    #pragma unroll
    for (int nt = 0; nt < 5; nt++) {
        ins5(top[0], c[nt][0]); ins5(top[0], c[nt][1]);
        ins5(top[1], c[nt][2]); ins5(top[1], c[nt][3]);
    }
    #pragma unroll
    for (int off = 1; off <= 2; off <<= 1) {
        #pragma unroll
        for (int r = 0; r < 2; r++) {
            float other[TOPK];
            #pragma unroll
            for (int k = 0; k < TOPK; k++)
                other[k] = __shfl_xor_sync(0xffffffffu, top[r][k], off);
            #pragma unroll
            for (int k = 0; k < TOPK; k++) ins5(top[r], other[k]);
        }
    }

    __syncthreads();
    float (*cand)[10] = (float(*)[10])&AB[0][0][0];
    if ((lane & 3) == 0) {
        #pragma unroll
        for (int r = 0; r < 2; r++) {
            int row = mrow + r * 8;
            #pragma unroll
            for (int k = 0; k < TOPK; k++)
                cand[row][wn*TOPK + k] = top[r][k];
        }
    }
    __syncthreads();
    if (t < DIMC) {
        float t5[TOPK];
        #pragma unroll
        for (int k = 0; k < TOPK; k++) t5[k] = -FLT_MAX;
        #pragma unroll
        for (int i = 0; i < 10; i++) ins5(t5, cand[t][i]);
        float* dst = g_chc + ((size_t)(((b*QN + q)*WAYS + w)*4 + quarter))*DIMC*TOPK + t*TOPK;
        #pragma unroll
        for (int k = 0; k < TOPK; k++) dst[k] = t5[k];
    }
}

// ---------------- merge 4 quarter top-5s per d, sum over d -> sim_l ----------------
__global__ void __launch_bounds__(64) kmerge_kernel() {
    const int bqw = blockIdx.x;
    const int d = threadIdx.x;
    const float* base = g_chc + (size_t)bqw * 4 * DIMC * TOPK;
    float t5[TOPK];
    #pragma unroll
    for (int k = 0; k < TOPK; k++) t5[k] = -FLT_MAX;
    #pragma unroll
    for (int qt = 0; qt < 4; qt++)
        #pragma unroll
        for (int k = 0; k < TOPK; k++)
            ins5(t5, base[(qt*DIMC + d)*TOPK + k]);
    float s = t5[0] + t5[1] + t5[2] + t5[3] + t5[4];
    __shared__ float red[2];
    #pragma unroll
    for (int o = 16; o; o >>= 1) s += __shfl_xor_sync(0xffffffffu, s, o);
    if ((d & 31) == 0) red[d >> 5] = s;
    __syncthreads();
    if (d == 0) {
        int bq = bqw / WAYS, w = bqw % WAYS;
        g_feats[bq*LFE + WAYS + w] = red[0] + red[1];
    }
}

// ---------------- pixel-level sim v4: 3-stage pipeline, LDS.128 pairs, thin epilogue ----------------
__global__ void __launch_bounds__(256) kpix_kernel() {
    const int tile = blockIdx.x;
    const int w = blockIdx.y;
    const int bq = blockIdx.z;
    const int b = bq / QN;
    __shared__ __align__(16) __half As[64][72];
    __shared__ __align__(16) __half Bs[3][64][72];
    __shared__ float red[2];
    const int t = threadIdx.x, lane = t & 31, wid = t >> 5;
    const int wm = wid >> 1, wn = wid & 1;
    const int mrow = wm * 16 + (lane >> 2);
    const int pcol = 8 * (lane & 3);                 // f16 offset of thread's 16B pair-block
    const int h0 = tile * 64;
    const __half* __restrict__ qT = g_qnTH + (size_t)bq * HWC * DIMC;
    const __half* __restrict__ sT = g_snTH + (size_t)(b*NSUP + w*SHOTS) * HWC * DIMC;

    auto fillB = [&](int buf, int cb) {
        #pragma unroll
        for (int i = 0; i < 2; i++) {
            int idx = t + i * 256;
            int n = idx >> 3, seg = idx & 7;
            int j = cb + n;
            int jj = (j < SHW) ? j : 0;              // clamp; masked in last-iter epilogue
            int shot = jj / HWC;
            int h2 = jj - shot * HWC;
            const __half* src = sT + (size_t)(shot*HWC + h2) * DIMC + seg * 8;
            cp_async16((uint32_t)__cvta_generic_to_shared(&Bs[buf][n][seg*8]), src);
        }
        cp_commit();
    };

    // prologue: A, B0, B1
    #pragma unroll
    for (int i = 0; i < 2; i++) {
        int idx = t + i * 256;
        int m = idx >> 3, seg = idx & 7;
        int h = h0 + m;
        const __half* src = qT + (size_t)((h < HWC) ? h : 0) * DIMC + seg * 8;
        cp_async16((uint32_t)__cvta_generic_to_shared(&As[m][seg*8]), src);
    }
    cp_commit();
    fillB(0, 0);
    fillB(1, 64);
    asm volatile("cp.async.wait_group 2;");          // A ready
    __syncthreads();

    // A fragments: per row-tile r and ks-pair p, one uint4 (even+odd quads)
    uint4 aF[2][2];
    #pragma unroll
    for (int r = 0; r < 2; r++)
        #pragma unroll
        for (int p = 0; p < 2; p++)
            aF[r][p] = *(const uint4*)&As[mrow + 8*r][32*p + pcol];
    // As never rewritten; no extra sync needed.

    float top[2][TOPK];
    #pragma unroll
    for (int r = 0; r < 2; r++)
        #pragma unroll
        for (int k = 0; k < TOPK; k++) top[r][k] = -FLT_MAX;

    for (int it = 0; it < 35; it++) {
        const int cur = it % 3;
        if (it < 34) asm volatile("cp.async.wait_group 1;");  // chunk(it) ready
        else         asm volatile("cp.async.wait_group 0;");
        __syncthreads();                                      // data visible; prev iter's reads of buf[(it+2)%3] done
        if (it + 2 <= 34) fillB((it + 2) % 3, (it + 2) * 64);

        float c[4][4];
        #pragma unroll
        for (int p = 0; p < 2; p++) {
            uint4 aLo = aF[0][p], aHi = aF[1][p];
            #pragma unroll
            for (int nt = 0; nt < 4; nt++) {
                uint4 bb = *(const uint4*)&Bs[cur][wn*32 + nt*8 + (lane>>2)][32*p + pcol];
                if (p == 0)
                    mma_f16_z(c[nt][0], c[nt][1], c[nt][2], c[nt][3],
                              aLo.x, aHi.x, aLo.y, aHi.y, bb.x, bb.y);
                else
                    mma_f16(c[nt][0], c[nt][1], c[nt][2], c[nt][3],
                            aLo.x, aHi.x, aLo.y, aHi.y, bb.x, bb.y);
                mma_f16(c[nt][0], c[nt][1], c[nt][2], c[nt][3],
                        aLo.z, aHi.z, aLo.w, aHi.w, bb.z, bb.w);
            }
        }

        if (it < 34) {                               // all 64 cols valid: unguarded
            #pragma unroll
            for (int nt = 0; nt < 4; nt++) {
                ins5(top[0], c[nt][0]); ins5(top[0], c[nt][1]);
                ins5(top[1], c[nt][2]); ins5(top[1], c[nt][3]);
            }
        } else {                                     // cb=2176: mask cols >= 2205
            const int cb = 34 * 64;
            #pragma unroll
            for (int nt = 0; nt < 4; nt++) {
                int col0 = cb + wn*32 + nt*8 + 2*(lane & 3);
                if (col0 < SHW)     { ins5(top[0], c[nt][0]); ins5(top[1], c[nt][2]); }
                if (col0 + 1 < SHW) { ins5(top[0], c[nt][1]); ins5(top[1], c[nt][3]); }
            }
        }
    }

    #pragma unroll
    for (int off = 1; off <= 2; off <<= 1) {
        #pragma unroll
        for (int r = 0; r < 2; r++) {
            float other[TOPK];
            #pragma unroll
            for (int k = 0; k < TOPK; k++)
                other[k] = __shfl_xor_sync(0xffffffffu, top[r][k], off);
            #pragma unroll
            for (int k = 0; k < TOPK; k++) ins5(top[r], other[k]);
        }
    }

    __syncthreads();
    float (*cand)[10] = (float(*)[10])&Bs[0][0][0];
    if ((lane & 3) == 0) {
        #pragma unroll
        for (int r = 0; r < 2; r++) {
            int row = mrow + r * 8;
            #pragma unroll
            for (int k = 0; k < TOPK; k++)
                cand[row][wn*TOPK + k] = top[r][k];
        }
    }
    __syncthreads();

    float rowsum = 0.f;
    if (t < 64) {
        if (h0 + t < HWC) {
            float t5[TOPK];
            #pragma unroll
            for (int k = 0; k < TOPK; k++) t5[k] = -FLT_MAX;
            #pragma unroll
            for (int i = 0; i < 10; i++) ins5(t5, cand[t][i]);
            rowsum = t5[0] + t5[1] + t5[2] + t5[3] + t5[4];
        }
        #pragma unroll
        for (int o = 16; o; o >>= 1) rowsum += __shfl_xor_sync(0xffffffffu, rowsum, o);
        if ((t & 31) == 0) red[t >> 5] = rowsum;
    }
    __syncthreads();
    if (t == 0) g_pix[((size_t)bq*WAYS + w)*NTILE + tile] = red[0] + red[1];
}

// ---------------- BN (batch stats) + dilated conv ----------------
__global__ void __launch_bounds__(256) kfin_kernel(const float* __restrict__ gamma,
                                                   const float* __restrict__ beta,
                                                   const float* __restrict__ cw,
                                                   float* __restrict__ out) {
    const int b = blockIdx.x;
    __shared__ float f[QN][LFE];
    __shared__ float mu[LFE], iv[LFE];
    const int t = threadIdx.x;
    for (int i = t; i < QN * WAYS; i += 256) {
        int q = i / WAYS, w = i - q * WAYS;
        const float* fr = &g_feats[(b*QN + q)*LFE];
        f[q][w]     = fr[w];
        f[q][5 + w] = fr[5 + w];
        float s = 0.f;
        #pragma unroll
        for (int j = 0; j < NTILE; j++)
            s += g_pix[((size_t)(b*QN + q)*WAYS + w)*NTILE + j];
        f[q][10 + w] = s;
    }
    __syncthreads();
    if (t < LFE) {
        float m = 0.f;
        for (int q = 0; q < QN; q++) m += f[q][t];
        m *= (1.0f / QN);
        float v = 0.f;
        for (int q = 0; q < QN; q++) { float d = f[q][t] - m; v = fmaf(d, d, v); }
        v *= (1.0f / QN);
        mu[t] = m;
        iv[t] = 1.0f / sqrtf(v + 1e-5f);
    }
    __syncthreads();
    float w0 = cw[0], w1 = cw[1], w2 = cw[2];
    for (int i = t; i < QN * WAYS; i += 256) {
        int q = i / WAYS, c = i - q * WAYS;
        float b0 = (f[q][c]      - mu[c])      * iv[c]      * gamma[c]      + beta[c];
        float b1 = (f[q][c + 5]  - mu[c + 5])  * iv[c + 5]  * gamma[c + 5]  + beta[c + 5];
        float b2 = (f[q][c + 10] - mu[c + 10]) * iv[c + 10] * gamma[c + 10] + beta[c + 10];
        out[(b*QN + q)*WAYS + c] = w0*b0 + w1*b1 + w2*b2;
    }
}

// ---------------- launch ----------------
extern "C" void kernel_launch(void* const* d_in, const int* in_sizes, int n_in,
                              void* d_out, int out_size) {
    const float* q     = (const float*)d_in[0];
    const float* s     = (const float*)d_in[1];
    const float* gamma = (const float*)d_in[2];
    const float* beta  = (const float*)d_in[3];
    const float* cw    = (const float*)d_in[4];
    float* out = (float*)d_out;

    knorm_kernel<0><<<BB*QN, 256>>>(q);
    knorm_kernel<1><<<BB*NSUP, 256>>>(s);
    kcos_kernel<<<BB, 256>>>();
    kchan_kernel<<<dim3(20, QN, BB), 256>>>();
    kpix_kernel<<<dim3(NTILE, WAYS, BB*QN), 256>>>();
    kmerge_kernel<<<BB*QN*WAYS, 64>>>();
    kfin_kernel<<<BB, 256>>>(gamma, beta, cw, out);
}